// round 14
// baseline (speedup 1.0000x reference)
#include <cuda_runtime.h>
#include <cuda_fp16.h>
#include <math.h>
#include <stdint.h>

#define Nn 20000
#define Rr 400
#define Hh 200
#define Ee 200000
#define Tt 3
#define Bb 1024
#define Cc 50
#define CH (Cc*Hh)
#define KSPLIT 10
#define NBLK ((Nn + 255) / 256)
#define SLOPEC 0.22916666666666666f
#define EPSN 1e-12f

// ---------------- scratch (device globals; no allocation allowed) ----------------
__device__ float g_ent[Nn*Hh];
__device__ float g_entB[Nn*Hh];
__device__ __half g_entH[Nn*Hh];
__device__ float g_h1[Nn*Hh];
__device__ __half g_h1H[Nn*Hh];
__device__ float g_h2[Nn*Hh];
__device__ float g_pre[Nn*Hh];
__device__ float g_preR[Nn*Hh];
__device__ float g_relh[Rr*Hh];
__device__ float g_x[Rr*2*Hh];
__device__ float g_gi[Rr*3*Hh];
__device__ float g_gh[Rr*3*Hh];
__device__ float g_nrel[Rr*Hh];
// per-timestep (x3) preprocessing buffers
__device__ int   g_relCnt[Tt*Rr];
__device__ int   g_relBase[Tt*(Rr+1)];
__device__ int   g_relCur[Tt*Rr];
__device__ int   g_edgeByRel[Tt*Ee];
__device__ int   g_degCnt[Tt*Nn];
__device__ int   g_nodeBase[Tt*(Nn+1)];
__device__ int   g_nodeCur[Tt*Nn];
__device__ int   g_edgeByDst[Tt*Ee];
__device__ int   g_blkSum[Tt*NBLK];
__device__ int   g_blkOff[Tt*NBLK];
__device__ float g_rnorm[Tt*Nn];
__device__ int   g_zeroList[Tt*Nn];
__device__ int   g_zeroCnt[Tt];
// decoder
__device__ __half g_featA[Bb*CH];
__device__ __half g_featB[Bb*CH];
__device__ float g_decA[Bb*Hh];
__device__ float g_decB[Bb*Hh];
__device__ float g_partA[KSPLIT*Bb*Hh];
__device__ float g_partB[KSPLIT*Bb*Hh];

// ---------------- tf32 helpers ----------------
__device__ __forceinline__ float to_tf32(float x) {
    uint32_t u;
    asm("cvt.rna.tf32.f32 %0, %1;" : "=r"(u) : "r"(__float_as_uint(x)));
    return __uint_as_float(u);
}

__device__ __forceinline__ void mma_tf32(float* d, const uint32_t* a, const uint32_t* b) {
    asm volatile(
        "mma.sync.aligned.m16n8k8.row.col.f32.tf32.tf32.f32 "
        "{%0,%1,%2,%3}, {%4,%5,%6,%7}, {%8,%9}, {%0,%1,%2,%3};\n"
        : "+f"(d[0]), "+f"(d[1]), "+f"(d[2]), "+f"(d[3])
        : "r"(a[0]), "r"(a[1]), "r"(a[2]), "r"(a[3]),
          "r"(b[0]), "r"(b[1]));
}

// predicated 8-float row load into regs
__device__ __forceinline__ void ld_row8(const float* __restrict__ base, int gka, int kmax,
                                        bool ok, float* r) {
    if (ok && gka + 8 <= kmax) {
        float4 v0 = *reinterpret_cast<const float4*>(base + gka);
        float4 v1 = *reinterpret_cast<const float4*>(base + gka + 4);
        r[0]=v0.x; r[1]=v0.y; r[2]=v0.z; r[3]=v0.w;
        r[4]=v1.x; r[5]=v1.y; r[6]=v1.z; r[7]=v1.w;
    } else {
#pragma unroll
        for (int q = 0; q < 8; q++) r[q] = (ok && gka + q < kmax) ? base[gka + q] : 0.f;
    }
}

// predicated 4-float row load into regs
__device__ __forceinline__ void ld_row4(const float* __restrict__ base, int gkw, int kmax,
                                        bool ok, float* r) {
    if (ok && gkw + 4 <= kmax) {
        float4 v = *reinterpret_cast<const float4*>(base + gkw);
        r[0]=v.x; r[1]=v.y; r[2]=v.z; r[3]=v.w;
    } else {
#pragma unroll
        for (int q = 0; q < 4; q++) r[q] = (ok && gkw + q < kmax) ? base[gkw + q] : 0.f;
    }
}

// predicated 8-half row load into regs (as floats)
__device__ __forceinline__ void ld_row8h(const __half* __restrict__ base, int gka, int kmax,
                                         bool ok, float* r) {
    if (ok && gka + 8 <= kmax) {
        uint4 raw = *reinterpret_cast<const uint4*>(base + gka);
        float2 f0 = __half22float2(*reinterpret_cast<__half2*>(&raw.x));
        float2 f1 = __half22float2(*reinterpret_cast<__half2*>(&raw.y));
        float2 f2 = __half22float2(*reinterpret_cast<__half2*>(&raw.z));
        float2 f3 = __half22float2(*reinterpret_cast<__half2*>(&raw.w));
        r[0]=f0.x; r[1]=f0.y; r[2]=f1.x; r[3]=f1.y;
        r[4]=f2.x; r[5]=f2.y; r[6]=f3.x; r[7]=f3.y;
    } else {
#pragma unroll
        for (int q = 0; q < 8; q++) r[q] = (ok && gka + q < kmax) ? __half2float(base[gka + q]) : 0.f;
    }
}

// ---------------- batched (all timesteps) preprocessing ----------------

__global__ void zero_prep3() {
    int tt = blockIdx.y;
    int i = blockIdx.x * blockDim.x + threadIdx.x;
    if (i < Nn) g_degCnt[tt*Nn + i] = 0;
    if (i < Rr) g_relCnt[tt*Rr + i] = 0;
    if (i == 0) g_zeroCnt[tt] = 0;
}

__global__ void hist3(const int* __restrict__ erel_all, const int* __restrict__ dst_all) {
    int tt = blockIdx.y;
    const int* er = erel_all + tt*Ee;
    const int* ds = dst_all + tt*Ee;
    __shared__ int sh[Rr];
    for (int i = threadIdx.x; i < Rr; i += blockDim.x) sh[i] = 0;
    __syncthreads();
    for (int e = blockIdx.x * blockDim.x + threadIdx.x; e < Ee; e += gridDim.x * blockDim.x) {
        atomicAdd(&sh[er[e]], 1);
        atomicAdd(&g_degCnt[tt*Nn + ds[e]], 1);
    }
    __syncthreads();
    for (int i = threadIdx.x; i < Rr; i += blockDim.x)
        if (sh[i]) atomicAdd(&g_relCnt[tt*Rr + i], sh[i]);
}

__global__ void scan_a3() {
    int tt = blockIdx.y;
    int b = blockIdx.x, t = threadIdx.x, i = b*256 + t;
    int v = (i < Nn) ? g_degCnt[tt*Nn + i] : 0;
    int lane = t & 31, w = t >> 5;
    int s = v;
#pragma unroll
    for (int o = 1; o < 32; o <<= 1) {
        int y = __shfl_up_sync(0xffffffffu, s, o);
        if (lane >= o) s += y;
    }
    __shared__ int wsum[8];
    if (lane == 31) wsum[w] = s;
    __syncthreads();
    if (w == 0 && lane < 8) {
        int x = wsum[lane];
#pragma unroll
        for (int o = 1; o < 8; o <<= 1) {
            int y = __shfl_up_sync(0xffu, x, o);
            if (lane >= o) x += y;
        }
        wsum[lane] = x;
    }
    __syncthreads();
    int incl = s + (w > 0 ? wsum[w-1] : 0);
    if (i < Nn) g_nodeBase[tt*(Nn+1) + i] = incl - v;
    if (t == 255) g_blkSum[tt*NBLK + b] = incl;
}

__global__ void scan_mid3() {
    int tt = blockIdx.y;
    __shared__ int sm[512];
    int t = threadIdx.x;
    if (blockIdx.x == 0) {
        int v = (t < NBLK) ? g_blkSum[tt*NBLK + t] : 0;
        sm[t] = v;
        __syncthreads();
        for (int o = 1; o < 512; o <<= 1) {
            int y = (t >= o) ? sm[t-o] : 0;
            __syncthreads();
            sm[t] += y;
            __syncthreads();
        }
        if (t < NBLK) g_blkOff[tt*NBLK + t] = sm[t] - v;
    } else {
        int v = (t < Rr) ? g_relCnt[tt*Rr + t] : 0;
        sm[t] = v;
        __syncthreads();
        for (int o = 1; o < 512; o <<= 1) {
            int y = (t >= o) ? sm[t-o] : 0;
            __syncthreads();
            sm[t] += y;
            __syncthreads();
        }
        if (t < Rr) { int e = sm[t] - v; g_relBase[tt*(Rr+1) + t] = e; g_relCur[tt*Rr + t] = e; }
        if (t == 0) g_relBase[tt*(Rr+1) + Rr] = Ee;
    }
}

__global__ void scan_c3() {
    int tt = blockIdx.y;
    int b = blockIdx.x, i = b*256 + threadIdx.x;
    if (i < Nn) {
        int x = g_nodeBase[tt*(Nn+1) + i] + g_blkOff[tt*NBLK + b];
        g_nodeBase[tt*(Nn+1) + i] = x;
        g_nodeCur[tt*Nn + i] = x;
        int d = g_degCnt[tt*Nn + i];
        g_rnorm[tt*Nn + i] = d > 0 ? 1.0f / (float)d : 0.0f;
        if (d == 0) {
            int k = atomicAdd(&g_zeroCnt[tt], 1);
            g_zeroList[tt*Nn + k] = i;
        }
    }
    if (i == 0) g_nodeBase[tt*(Nn+1) + Nn] = Ee;
}

__global__ void scatter3(const int* __restrict__ erel_all, const int* __restrict__ dst_all) {
    int tt = blockIdx.y;
    const int* er = erel_all + tt*Ee;
    const int* ds = dst_all + tt*Ee;
    int e = blockIdx.x * blockDim.x + threadIdx.x;
    if (e < Ee) {
        int p1 = atomicAdd(&g_relCur[tt*Rr + er[e]], 1);
        g_edgeByRel[tt*Ee + p1] = e;
        int p2 = atomicAdd(&g_nodeCur[tt*Nn + ds[e]], 1);
        g_edgeByDst[tt*Ee + p2] = e;
    }
}

// ---------------- utility kernels ----------------

__global__ void normalize_rows(const float* __restrict__ in, float* __restrict__ out,
                               __half* __restrict__ outH, int rows) {
    int r = blockIdx.x;
    if (r >= rows) return;
    __shared__ float red[256];
    int t = threadIdx.x;
    float v = (t < Hh) ? in[r*Hh + t] : 0.f;
    red[t] = v*v;
    __syncthreads();
    for (int s = 128; s > 0; s >>= 1) { if (t < s) red[t] += red[t+s]; __syncthreads(); }
    float inv = 1.0f / fmaxf(sqrtf(red[0]), EPSN);
    if (t < Hh) {
        float x = v * inv;
        out[r*Hh + t] = x;
        if (outH) outH[r*Hh + t] = __float2half_rn(x);
    }
}

// per-relation mean of entH[src] + build GRU input x
__global__ void rel_mean(const int* __restrict__ srcT, const __half2* __restrict__ entH2,
                         const float* __restrict__ rel_embeds,
                         const int* __restrict__ relBase, const int* __restrict__ edgeByRel) {
    __shared__ int ss[256];
    int r = blockIdx.x, t = threadIdx.x;
    int b0 = relBase[r], b1 = relBase[r+1];
    float2 acc = make_float2(0.f, 0.f);
    for (int cb = b0; cb < b1; cb += 256) {
        int m = min(256, b1 - cb);
        if (t < m) ss[t] = srcT[edgeByRel[cb + t]];
        __syncthreads();
        if (t < Hh/2) {
#pragma unroll 4
            for (int i = 0; i < m; i++) {
                float2 f = __half22float2(entH2[ss[i]*(Hh/2) + t]);
                acc.x += f.x; acc.y += f.y;
            }
        }
        __syncthreads();
    }
    if (t < Hh) g_x[r*2*Hh + t] = rel_embeds[r*Hh + t];
    if (t < Hh/2) {
        int cnt = b1 - b0;
        float invc = cnt > 0 ? 1.0f / (float)cnt : 0.f;
        g_x[r*2*Hh + Hh + 2*t]     = acc.x * invc;
        g_x[r*2*Hh + Hh + 2*t + 1] = acc.y * invc;
    }
}

// GRU gates + l2norm; writes n_rel and relh
__global__ void gru_gate() {
    int r = blockIdx.x, t = threadIdx.x;
    __shared__ float red[256];
    float hp = 0.f;
    if (t < Hh) {
        const float* gi = &g_gi[r*3*Hh];
        const float* gh = &g_gh[r*3*Hh];
        float h  = g_relh[r*Hh + t];
        float rr = 1.f / (1.f + expf(-(gi[t]        + gh[t])));
        float z  = 1.f / (1.f + expf(-(gi[Hh+t]     + gh[Hh+t])));
        float n  = tanhf(gi[2*Hh+t] + rr * gh[2*Hh+t]);
        hp = (1.f - z) * n + z * h;
    }
    red[t] = hp*hp;
    __syncthreads();
    for (int s = 128; s > 0; s >>= 1) { if (t < s) red[t] += red[t+s]; __syncthreads(); }
    float inv = 1.0f / fmaxf(sqrtf(red[0]), EPSN);
    if (t < Hh) {
        float v = hp * inv;
        g_nrel[r*Hh + t] = v;
        g_relh[r*Hh + t] = v;
    }
}

// gather_h: pre[n] = sum over in-edges of hinH[src]
__global__ void gather_h(const int* __restrict__ srcT, const __half2* __restrict__ hinH2,
                         const int* __restrict__ nodeBase, const int* __restrict__ edgeByDst) {
    __shared__ int ss[2][32];
    __shared__ int maxlen;
    int half_id = threadIdx.x >> 7;
    int t = threadIdx.x & 127;
    int n = blockIdx.x * 2 + half_id;
    int b0 = nodeBase[n], b1 = nodeBase[n+1];
    int len = b1 - b0;
    if (threadIdx.x == 0) maxlen = 0;
    __syncthreads();
    if (t == 0) atomicMax(&maxlen, len);
    __syncthreads();
    float2 acc = make_float2(0.f, 0.f);
    int ml = maxlen;
    for (int cb = 0; cb < ml; cb += 32) {
        int m = min(32, len - cb);
        if (t < m) ss[half_id][t] = srcT[edgeByDst[b0 + cb + t]];
        __syncthreads();
        if (t < Hh/2) {
#pragma unroll 4
            for (int i = 0; i < m; i++) {
                float2 h = __half22float2(hinH2[ss[half_id][i]*(Hh/2) + t]);
                acc.x += h.x; acc.y += h.y;
            }
        }
        __syncthreads();
    }
    if (t < Hh/2) ((float2*)g_pre)[n*(Hh/2) + t] = acc;
}

// gather_radd: preR[n] = sum over in-edges of nrel[erel]   (once per step, reused by both layers)
__global__ void gather_radd(const int* __restrict__ erelT,
                            const int* __restrict__ nodeBase, const int* __restrict__ edgeByDst) {
    __shared__ int rs[2][32];
    __shared__ int maxlen;
    int half_id = threadIdx.x >> 7;
    int t = threadIdx.x & 127;
    int n = blockIdx.x * 2 + half_id;
    int b0 = nodeBase[n], b1 = nodeBase[n+1];
    int len = b1 - b0;
    if (threadIdx.x == 0) maxlen = 0;
    __syncthreads();
    if (t == 0) atomicMax(&maxlen, len);
    __syncthreads();
    const float2* nrel2 = (const float2*)g_nrel;
    float2 acc = make_float2(0.f, 0.f);
    int ml = maxlen;
    for (int cb = 0; cb < ml; cb += 32) {
        int m = min(32, len - cb);
        if (t < m) rs[half_id][t] = erelT[edgeByDst[b0 + cb + t]];
        __syncthreads();
        if (t < Hh/2) {
#pragma unroll 4
            for (int i = 0; i < m; i++) {
                float2 r = nrel2[rs[half_id][i]*(Hh/2) + t];
                acc.x += r.x; acc.y += r.y;
            }
        }
        __syncthreads();
    }
    if (t < Hh/2) ((float2*)g_preR)[n*(Hh/2) + t] = acc;
}

// deg==0 rows: out = rrelu(hin @ Wel^T)
__global__ void fixup_zero(const float* __restrict__ Wel, const float* __restrict__ hin,
                           float* __restrict__ hout, __half* __restrict__ houtH,
                           const int* __restrict__ zeroList, const int* __restrict__ zeroCnt) {
    __shared__ float hrow[Hh];
    int zc = *zeroCnt;
    for (int li = blockIdx.x; li < zc; li += gridDim.x) {
        int n = zeroList[li];
        int t = threadIdx.x;
        if (t < Hh) hrow[t] = hin[n*Hh + t];
        __syncthreads();
        if (t < Hh) {
            float s = 0.f;
            for (int k = 0; k < Hh; k++) s += hrow[k] * Wel[t*Hh + k];
            s = s >= 0.f ? s : SLOPEC * s;
            hout[n*Hh + t] = s;
            if (houtH) houtH[n*Hh + t] = __float2half_rn(s);
        }
        __syncthreads();
    }
}

// ---------------- fused RGCN layer (double-buffered, dynamic smem) ----------------
// pre operand = pre[] + preR[]  (h-gather + shared nrel-gather)
#define FPA 136
#define FPW 72
#define RGCN_SMEM_FLOATS (4*16*FPA + 4*16*FPW)
#define RGCN_SMEM_BYTES (RGCN_SMEM_FLOATS * 4)
__global__ void __launch_bounds__(256)
rgcn_fused(const float* __restrict__ hin, const float* __restrict__ pre,
           const float* __restrict__ preR,
           const float* __restrict__ Wr, const float* __restrict__ Wsl,
           float* __restrict__ hout, __half* __restrict__ houtH,
           const float* __restrict__ rnorm) {
    extern __shared__ float dsm[];
    float (*Ah)[16][FPA] = (float(*)[16][FPA])(dsm);
    float (*Ap)[16][FPA] = (float(*)[16][FPA])(dsm + 2*16*FPA);
    float (*Sr)[16][FPW] = (float(*)[16][FPW])(dsm + 4*16*FPA);
    float (*Ss)[16][FPW] = (float(*)[16][FPW])(dsm + 4*16*FPA + 2*16*FPW);

    int tid = threadIdx.x;
    int j0 = blockIdx.x * 64;
    int i0 = blockIdx.y * 128;
    int wid = tid >> 5, lane = tid & 31;
    int wr = wid & 1, wc = wid >> 1;
    int gid = lane >> 2, tig = lane & 3;

    float accR[4][2][4], accS[4][2][4];
#pragma unroll
    for (int a = 0; a < 4; a++)
#pragma unroll
        for (int b = 0; b < 2; b++)
#pragma unroll
            for (int v = 0; v < 4; v++) { accR[a][b][v] = 0.f; accS[a][b][v] = 0.f; }

    int arow = tid >> 1;
    int akoff = (tid & 1) * 8;
    int gr = i0 + arow;
    bool rok = gr < Nn;
    const float* hrow = hin + (size_t)gr * Hh;
    const float* prow = pre + (size_t)gr * Hh;
    const float* qrow = preR + (size_t)gr * Hh;

    int wrow = tid >> 2;
    int wkoff = (tid & 3) * 4;
    int gw = j0 + wrow;
    bool wok = gw < Hh;
    const float* wrp = Wr  + (size_t)gw * Hh;
    const float* wsp = Wsl + (size_t)gw * Hh;

    const int NK = (Hh + 15) / 16;   // 13
    float rh[8], rp[8], rq[8], rr4[4], rs4[4];

    ld_row8(hrow, akoff, Hh, rok, rh);
    ld_row8(prow, akoff, Hh, rok, rp);
    ld_row8(qrow, akoff, Hh, rok, rq);
    ld_row4(wrp, wkoff, Hh, wok, rr4);
    ld_row4(wsp, wkoff, Hh, wok, rs4);
#pragma unroll
    for (int q = 0; q < 8; q++) { Ah[0][akoff+q][arow] = to_tf32(rh[q]); Ap[0][akoff+q][arow] = to_tf32(rp[q] + rq[q]); }
#pragma unroll
    for (int q = 0; q < 4; q++) { Sr[0][wkoff+q][wrow] = to_tf32(rr4[q]); Ss[0][wkoff+q][wrow] = to_tf32(rs4[q]); }
    __syncthreads();

    for (int it = 0; it < NK; it++) {
        int cur = it & 1;
        bool more = (it + 1 < NK);
        if (more) {
            int kt = (it + 1) * 16;
            ld_row8(hrow, kt + akoff, Hh, rok, rh);
            ld_row8(prow, kt + akoff, Hh, rok, rp);
            ld_row8(qrow, kt + akoff, Hh, rok, rq);
            ld_row4(wrp, kt + wkoff, Hh, wok, rr4);
            ld_row4(wsp, kt + wkoff, Hh, wok, rs4);
        }
#pragma unroll
        for (int kk = 0; kk < 16; kk += 8) {
            uint32_t ah[4][4], ap[4][4];
#pragma unroll
            for (int mt = 0; mt < 4; mt++) {
                int r0 = wr*64 + mt*16 + gid;
                ah[mt][0] = __float_as_uint(Ah[cur][kk+tig  ][r0]);
                ah[mt][1] = __float_as_uint(Ah[cur][kk+tig  ][r0+8]);
                ah[mt][2] = __float_as_uint(Ah[cur][kk+tig+4][r0]);
                ah[mt][3] = __float_as_uint(Ah[cur][kk+tig+4][r0+8]);
                ap[mt][0] = __float_as_uint(Ap[cur][kk+tig  ][r0]);
                ap[mt][1] = __float_as_uint(Ap[cur][kk+tig  ][r0+8]);
                ap[mt][2] = __float_as_uint(Ap[cur][kk+tig+4][r0]);
                ap[mt][3] = __float_as_uint(Ap[cur][kk+tig+4][r0+8]);
            }
            uint32_t br[2][2], bs[2][2];
#pragma unroll
            for (int nt = 0; nt < 2; nt++) {
                int cn = wc*16 + nt*8 + gid;
                br[nt][0] = __float_as_uint(Sr[cur][kk+tig  ][cn]);
                br[nt][1] = __float_as_uint(Sr[cur][kk+tig+4][cn]);
                bs[nt][0] = __float_as_uint(Ss[cur][kk+tig  ][cn]);
                bs[nt][1] = __float_as_uint(Ss[cur][kk+tig+4][cn]);
            }
#pragma unroll
            for (int mt = 0; mt < 4; mt++)
#pragma unroll
                for (int nt = 0; nt < 2; nt++) {
                    mma_tf32(accR[mt][nt], ap[mt], br[nt]);
                    mma_tf32(accS[mt][nt], ah[mt], bs[nt]);
                }
        }
        if (more) {
            int nxt = 1 - cur;
#pragma unroll
            for (int q = 0; q < 8; q++) { Ah[nxt][akoff+q][arow] = to_tf32(rh[q]); Ap[nxt][akoff+q][arow] = to_tf32(rp[q] + rq[q]); }
#pragma unroll
            for (int q = 0; q < 4; q++) { Sr[nxt][wkoff+q][wrow] = to_tf32(rr4[q]); Ss[nxt][wkoff+q][wrow] = to_tf32(rs4[q]); }
            __syncthreads();
        }
    }

#pragma unroll
    for (int mt = 0; mt < 4; mt++) {
#pragma unroll
        for (int nt = 0; nt < 2; nt++) {
            int rbase = i0 + wr*64 + mt*16 + gid;
            int cbase = j0 + wc*16 + nt*8 + tig*2;
#pragma unroll
            for (int v = 0; v < 4; v++) {
                int row = rbase + ((v >= 2) ? 8 : 0);
                int col = cbase + (v & 1);
                if (row >= Nn || col >= Hh) continue;
                float x = accR[mt][nt][v] * rnorm[row] + accS[mt][nt][v];
                x = x >= 0.f ? x : SLOPEC * x;
                hout[(size_t)row * Hh + col] = x;
                if (houtH) houtH[(size_t)row * Hh + col] = __float2half_rn(x);
            }
        }
    }
}

// ---------------- tf32 GEMM (fp32 A), double-buffered: C = epi(A @ W^T) ----------------
// EPI: 0 plain | 4 acc+bias | 5 fused gate-update (computes row norms of Sadd internally)
#define TPAD 136
template<int EPI>
__global__ void __launch_bounds__(256)
tgemm(const float* __restrict__ A, const float* __restrict__ W,
      float* __restrict__ C, int M, int Nout, int Kdim,
      const float* __restrict__ bias,
      const float* __restrict__ Sadd,
      __half* __restrict__ Chalf) {
    __shared__ float As[2][16][TPAD];
    __shared__ float Ws[2][16][TPAD];
    __shared__ float winv_s[128];
    int tid = threadIdx.x;
    int j0 = blockIdx.x * 128;
    int i0 = blockIdx.y * 128;

    int wid = tid >> 5, lane = tid & 31;
    int wr = wid & 1, wc = wid >> 1;
    int gid = lane >> 2, tig = lane & 3;

    float acc[4][4][4];
#pragma unroll
    for (int a = 0; a < 4; a++)
#pragma unroll
        for (int b = 0; b < 4; b++)
#pragma unroll
            for (int v = 0; v < 4; v++) acc[a][b][v] = 0.f;

    int arow = tid >> 1;
    int akoff = (tid & 1) * 8;
    int gr = i0 + arow;
    int gw = j0 + arow;
    bool rok = gr < M;
    bool wok = gw < Nout;
    const float* Arow_p = A + (size_t)gr * Kdim;
    const float* Wrow_p = W + (size_t)gw * Kdim;

    const int NK = (Kdim + 15) / 16;
    float ra[8], rw[8];

    ld_row8(Arow_p, akoff, Kdim, rok, ra);
    ld_row8(Wrow_p, akoff, Kdim, wok, rw);
#pragma unroll
    for (int q = 0; q < 8; q++) { As[0][akoff+q][arow] = to_tf32(ra[q]); Ws[0][akoff+q][arow] = to_tf32(rw[q]); }

    if (EPI == 5) {
        // per-row l2-norm inverse of Sadd rows i0..i0+127 (8 warps x 16 rows)
        for (int rr = wid*16; rr < wid*16 + 16; rr++) {
            int row = i0 + rr;
            float s = 0.f;
            if (row < M) {
                const float* srow = Sadd + (size_t)row * Nout;
                for (int c = lane; c < Nout; c += 32) { float v = srow[c]; s += v*v; }
            }
#pragma unroll
            for (int o = 16; o > 0; o >>= 1) s += __shfl_xor_sync(0xffffffffu, s, o);
            if (lane == 0) winv_s[rr] = 1.0f / fmaxf(sqrtf(s), EPSN);
        }
    }
    __syncthreads();

    for (int it = 0; it < NK; it++) {
        int cur = it & 1;
        bool more = (it + 1 < NK);
        if (more) {
            int kt = (it + 1) * 16;
            ld_row8(Arow_p, kt + akoff, Kdim, rok, ra);
            ld_row8(Wrow_p, kt + akoff, Kdim, wok, rw);
        }
#pragma unroll
        for (int kk = 0; kk < 16; kk += 8) {
            uint32_t af[4][4];
            uint32_t bf[4][2];
#pragma unroll
            for (int mt = 0; mt < 4; mt++) {
                int r0 = wr*64 + mt*16 + gid;
                af[mt][0] = __float_as_uint(As[cur][kk+tig  ][r0]);
                af[mt][1] = __float_as_uint(As[cur][kk+tig  ][r0+8]);
                af[mt][2] = __float_as_uint(As[cur][kk+tig+4][r0]);
                af[mt][3] = __float_as_uint(As[cur][kk+tig+4][r0+8]);
            }
#pragma unroll
            for (int nt = 0; nt < 4; nt++) {
                int cn = wc*32 + nt*8 + gid;
                bf[nt][0] = __float_as_uint(Ws[cur][kk+tig  ][cn]);
                bf[nt][1] = __float_as_uint(Ws[cur][kk+tig+4][cn]);
            }
#pragma unroll
            for (int mt = 0; mt < 4; mt++)
#pragma unroll
                for (int nt = 0; nt < 4; nt++)
                    mma_tf32(acc[mt][nt], af[mt], bf[nt]);
        }
        if (more) {
            int nxt = 1 - cur;
#pragma unroll
            for (int q = 0; q < 8; q++) { As[nxt][akoff+q][arow] = to_tf32(ra[q]); Ws[nxt][akoff+q][arow] = to_tf32(rw[q]); }
            __syncthreads();
        }
    }

#pragma unroll
    for (int mt = 0; mt < 4; mt++) {
#pragma unroll
        for (int nt = 0; nt < 4; nt++) {
            int rbase = i0 + wr*64 + mt*16 + gid;
            int cbase = j0 + wc*32 + nt*8 + tig*2;
#pragma unroll
            for (int v = 0; v < 4; v++) {
                int row = rbase + ((v >= 2) ? 8 : 0);
                int col = cbase + (v & 1);
                if (row >= M || col >= Nout) continue;
                float x = acc[mt][nt][v];
                if (EPI == 4) {
                    x += bias[col];
                } else if (EPI == 5) {
                    float u = 1.f / (1.f + expf(-(x + bias[col])));
                    float e = A[(size_t)row * Kdim + col];
                    float w = Sadd[(size_t)row * Nout + col] * winv_s[row - i0];
                    x = e + u * (w - e);
                    Chalf[(size_t)row * Nout + col] = __float2half_rn(x);
                }
                C[(size_t)row * Nout + col] = x;
            }
        }
    }
}

// ---------------- split-K GEMM with fp16 A (double-buffered): raw partials ----------------
__global__ void __launch_bounds__(256)
tgemmH_split(const __half* __restrict__ A, const float* __restrict__ W,
             float* __restrict__ C, int M, int Nout, int Kdim, int klen) {
    __shared__ float As[2][16][TPAD];
    __shared__ float Ws[2][16][TPAD];
    int tid = threadIdx.x;
    int j0 = blockIdx.x * 128;
    int i0 = blockIdx.y * 128;
    int k0 = blockIdx.z * klen;
    int k1 = min(Kdim, k0 + klen);

    int wid = tid >> 5, lane = tid & 31;
    int wr = wid & 1, wc = wid >> 1;
    int gid = lane >> 2, tig = lane & 3;

    float acc[4][4][4];
#pragma unroll
    for (int a = 0; a < 4; a++)
#pragma unroll
        for (int b = 0; b < 4; b++)
#pragma unroll
            for (int v = 0; v < 4; v++) acc[a][b][v] = 0.f;

    int arow = tid >> 1;
    int akoff = (tid & 1) * 8;
    int gr = i0 + arow;
    int gw = j0 + arow;
    bool rok = gr < M;
    bool wok = gw < Nout;
    const __half* Arow_p = A + (size_t)gr * Kdim;
    const float* Wrow_p = W + (size_t)gw * Kdim;

    const int NK = (k1 - k0 + 15) / 16;
    float ra[8], rw[8];

    ld_row8h(Arow_p, k0 + akoff, k1, rok, ra);
    ld_row8(Wrow_p, k0 + akoff, k1, wok, rw);
#pragma unroll
    for (int q = 0; q < 8; q++) { As[0][akoff+q][arow] = ra[q]; Ws[0][akoff+q][arow] = to_tf32(rw[q]); }
    __syncthreads();

    for (int it = 0; it < NK; it++) {
        int cur = it & 1;
        bool more = (it + 1 < NK);
        if (more) {
            int kt = k0 + (it + 1) * 16;
            ld_row8h(Arow_p, kt + akoff, k1, rok, ra);
            ld_row8(Wrow_p, kt + akoff, k1, wok, rw);
        }
#pragma unroll
        for (int kk = 0; kk < 16; kk += 8) {
            uint32_t af[4][4];
            uint32_t bf[4][2];
#pragma unroll
            for (int mt = 0; mt < 4; mt++) {
                int r0 = wr*64 + mt*16 + gid;
                af[mt][0] = __float_as_uint(As[cur][kk+tig  ][r0]);
                af[mt][1] = __float_as_uint(As[cur][kk+tig  ][r0+8]);
                af[mt][2] = __float_as_uint(As[cur][kk+tig+4][r0]);
                af[mt][3] = __float_as_uint(As[cur][kk+tig+4][r0+8]);
            }
#pragma unroll
            for (int nt = 0; nt < 4; nt++) {
                int cn = wc*32 + nt*8 + gid;
                bf[nt][0] = __float_as_uint(Ws[cur][kk+tig  ][cn]);
                bf[nt][1] = __float_as_uint(Ws[cur][kk+tig+4][cn]);
            }
#pragma unroll
            for (int mt = 0; mt < 4; mt++)
#pragma unroll
                for (int nt = 0; nt < 4; nt++)
                    mma_tf32(acc[mt][nt], af[mt], bf[nt]);
        }
        if (more) {
            int nxt = 1 - cur;
#pragma unroll
            for (int q = 0; q < 8; q++) { As[nxt][akoff+q][arow] = ra[q]; Ws[nxt][akoff+q][arow] = to_tf32(rw[q]); }
            __syncthreads();
        }
    }

    float* Cb = C + (size_t)blockIdx.z * M * Nout;
#pragma unroll
    for (int mt = 0; mt < 4; mt++) {
#pragma unroll
        for (int nt = 0; nt < 4; nt++) {
            int rbase = i0 + wr*64 + mt*16 + gid;
            int cbase = j0 + wc*32 + nt*8 + tig*2;
#pragma unroll
            for (int v = 0; v < 4; v++) {
                int row = rbase + ((v >= 2) ? 8 : 0);
                int col = cbase + (v & 1);
                if (row >= M || col >= Nout) continue;
                Cb[(size_t)row * Nout + col] = acc[mt][nt][v];
            }
        }
    }
}

// deterministic split-K reduction + bias + relu
__global__ void split_reduce_relu(const float* __restrict__ part, float* __restrict__ dst,
                                  const float* __restrict__ bias) {
    int i = blockIdx.x * blockDim.x + threadIdx.x;
    if (i < Bb*Hh) {
        float s = 0.f;
#pragma unroll
        for (int z = 0; z < KSPLIT; z++) s += part[(size_t)z * Bb * Hh + i];
        s += bias[i % Hh];
        dst[i] = fmaxf(s, 0.f);
    }
}

// ---------------- decoder: fused gather + conv + relu (fp16 feat out) ----------------
__global__ void conv_feat(const float* __restrict__ cw, const float* __restrict__ cb,
                          const int* __restrict__ sidx, const int* __restrict__ oidx,
                          const float* __restrict__ ent, const float* __restrict__ other,
                          __half* __restrict__ feat, int mode) {
    int b = blockIdx.x;
    __shared__ float s1[Hh+2], s2[Hh+2];
    __shared__ float w[Cc*6];
    __shared__ float bb[Cc];
    int t = threadIdx.x;
    if (t < Hh) {
        s1[t+1] = ent[sidx[b]*Hh + t];
        s2[t+1] = mode ? ent[oidx[b]*Hh + t] : other[oidx[b]*Hh + t];
    }
    if (t == 0) { s1[0] = 0.f; s2[0] = 0.f; s1[Hh+1] = 0.f; s2[Hh+1] = 0.f; }
    for (int i = t; i < Cc*6; i += blockDim.x) w[i] = cw[i];
    if (t < Cc) bb[t] = cb[t];
    __syncthreads();
    for (int idx = t; idx < CH; idx += blockDim.x) {
        int c = idx / Hh, i = idx % Hh;
        const float* wc = &w[c*6];
        float v = bb[c]
            + s1[i]*wc[0] + s1[i+1]*wc[1] + s1[i+2]*wc[2]
            + s2[i]*wc[3] + s2[i+1]*wc[4] + s2[i+2]*wc[5];
        feat[(size_t)b*CH + idx] = __float2half_rn(fmaxf(v, 0.f));
    }
}

// ---------------- host ----------------

static void* symaddr(const void* s) { void* p = nullptr; cudaGetSymbolAddress(&p, s); return p; }

extern "C" void kernel_launch(void* const* d_in, const int* in_sizes, int n_in,
                              void* d_out, int out_size) {
    const float* ent_embeds = (const float*)d_in[0];
    const float* rel_embeds = (const float*)d_in[1];
    const float* Wr1  = (const float*)d_in[2];
    const float* Wsl1 = (const float*)d_in[3];
    const float* Wel1 = (const float*)d_in[4];
    const float* Wr2  = (const float*)d_in[5];
    const float* Wsl2 = (const float*)d_in[6];
    const float* Wel2 = (const float*)d_in[7];
    const float* lin_W = (const float*)d_in[8];
    const float* lin_b = (const float*)d_in[9];
    const float* gru_Wih = (const float*)d_in[10];
    const float* gru_Whh = (const float*)d_in[11];
    const float* gru_bih = (const float*)d_in[12];
    const float* gru_bhh = (const float*)d_in[13];
    const float* conve_w = (const float*)d_in[14];
    const float* conve_b = (const float*)d_in[15];
    const float* fce_w = (const float*)d_in[16];
    const float* fce_b = (const float*)d_in[17];
    const float* convr_w = (const float*)d_in[18];
    const float* convr_b = (const float*)d_in[19];
    const float* fcr_w = (const float*)d_in[20];
    const float* fcr_b = (const float*)d_in[21];
    const int* src  = (const int*)d_in[22];
    const int* dst  = (const int*)d_in[23];
    const int* erel = (const int*)d_in[24];
    const int* subj = (const int*)d_in[25];
    const int* relI = (const int*)d_in[26];
    const int* objI = (const int*)d_in[27];
    float* out = (float*)d_out;

    float* p_entA  = (float*)symaddr(g_ent);
    float* p_entB  = (float*)symaddr(g_entB);
    __half* p_entH = (__half*)symaddr(g_entH);
    float* p_h1    = (float*)symaddr(g_h1);
    __half* p_h1H  = (__half*)symaddr(g_h1H);
    float* p_h2    = (float*)symaddr(g_h2);
    float* p_pre   = (float*)symaddr(g_pre);
    float* p_preR  = (float*)symaddr(g_preR);
    float* p_relh  = (float*)symaddr(g_relh);
    float* p_x     = (float*)symaddr(g_x);
    float* p_gi    = (float*)symaddr(g_gi);
    float* p_gh    = (float*)symaddr(g_gh);
    int* p_relBase = (int*)symaddr(g_relBase);
    int* p_edgeByRel = (int*)symaddr(g_edgeByRel);
    int* p_nodeBase = (int*)symaddr(g_nodeBase);
    int* p_edgeByDst = (int*)symaddr(g_edgeByDst);
    float* p_rnorm = (float*)symaddr(g_rnorm);
    int* p_zeroList = (int*)symaddr(g_zeroList);
    int* p_zeroCnt = (int*)symaddr(g_zeroCnt);
    __half* p_featA = (__half*)symaddr(g_featA);
    __half* p_featB = (__half*)symaddr(g_featB);
    float* p_decA  = (float*)symaddr(g_decA);
    float* p_decB  = (float*)symaddr(g_decB);
    float* p_partA = (float*)symaddr(g_partA);
    float* p_partB = (float*)symaddr(g_partB);

    const float* Wr_[2]  = {Wr1, Wr2};
    const float* Wsl_[2] = {Wsl1, Wsl2};
    const float* Wel_[2] = {Wel1, Wel2};

    #define TGX(Nc) (((Nc)+127)/128)
    #define TGY(Mr) (((Mr)+127)/128)

    // One-time stream/event creation + smem attribute (host-side resource
    // init; identical GPU work enqueued every call). Per-call creation
    // allocated device memory during graph capture → harness guard.
    static cudaStream_t sP = nullptr, sR = nullptr, s2 = nullptr;
    static cudaEvent_t evRoot, evPrep, evF, evJ, evE[Tt], evG[Tt];
    if (sP == nullptr) {
        cudaStreamCreate(&sP);
        cudaStreamCreate(&sR);
        cudaStreamCreate(&s2);
        cudaEventCreateWithFlags(&evRoot, cudaEventDisableTiming);
        cudaEventCreateWithFlags(&evPrep, cudaEventDisableTiming);
        cudaEventCreateWithFlags(&evF, cudaEventDisableTiming);
        cudaEventCreateWithFlags(&evJ, cudaEventDisableTiming);
        for (int t = 0; t < Tt; t++) {
            cudaEventCreateWithFlags(&evE[t], cudaEventDisableTiming);
            cudaEventCreateWithFlags(&evG[t], cudaEventDisableTiming);
        }
        cudaFuncSetAttribute(rgcn_fused, cudaFuncAttributeMaxDynamicSharedMemorySize, RGCN_SMEM_BYTES);
    }

    // ---- fork: batched 3-step edge preprocessing on sP ----
    cudaEventRecord(evRoot, 0);
    cudaStreamWaitEvent(sP, evRoot, 0);
    zero_prep3<<<dim3((Nn+255)/256, Tt), 256, 0, sP>>>();
    hist3<<<dim3(160, Tt), 256, 0, sP>>>(erel, dst);
    scan_a3<<<dim3(NBLK, Tt), 256, 0, sP>>>();
    scan_mid3<<<dim3(2, Tt), 512, 0, sP>>>();
    scan_c3<<<dim3(NBLK, Tt), 256, 0, sP>>>();
    scatter3<<<dim3((Ee+255)/256, Tt), 256, 0, sP>>>(erel, dst);
    cudaEventRecord(evPrep, sP);

    // ---- init (stream 0, concurrent with prep) ----
    normalize_rows<<<Nn, 256>>>(ent_embeds, p_entA, p_entH, Nn);
    normalize_rows<<<Rr, 256>>>(rel_embeds, p_relh, nullptr, Rr);
    cudaStreamWaitEvent(0, evPrep, 0);

    float* entIn = p_entA;
    float* entOut = p_entB;

    for (int t = 0; t < Tt; t++) {
        const int* srcT  = src  + t*Ee;
        const int* erelT = erel + t*Ee;
        const int* nbT   = p_nodeBase + t*(Nn+1);
        const int* ebdT  = p_edgeByDst + t*Ee;
        const int* rbT   = p_relBase + t*(Rr+1);
        const int* ebrT  = p_edgeByRel + t*Ee;
        const float* rnT = p_rnorm + t*Nn;
        const int* zlT   = p_zeroList + t*Nn;
        const int* zcT   = p_zeroCnt + t;

        // fork: relation-GRU path + preR gather on sR; big h-gather on stream 0
        cudaEventRecord(evE[t], 0);
        cudaStreamWaitEvent(sR, evE[t], 0);

        gather_h<<<Nn/2, 256>>>(srcT, (const __half2*)p_entH, nbT, ebdT);

        rel_mean<<<Rr, 256, 0, sR>>>(srcT, (const __half2*)p_entH, rel_embeds, rbT, ebrT);
        tgemm<4><<<dim3(TGX(3*Hh), TGY(Rr)), 256, 0, sR>>>(p_x, gru_Wih, p_gi, Rr, 3*Hh, 2*Hh, gru_bih, nullptr, nullptr);
        tgemm<4><<<dim3(TGX(3*Hh), TGY(Rr)), 256, 0, sR>>>(p_relh, gru_Whh, p_gh, Rr, 3*Hh, Hh, gru_bhh, nullptr, nullptr);
        gru_gate<<<Rr, 256, 0, sR>>>();
        gather_radd<<<Nn/2, 256, 0, sR>>>(erelT, nbT, ebdT);   // preR, reused by BOTH layers
        cudaEventRecord(evG[t], sR);
        cudaStreamWaitEvent(0, evG[t], 0);

        rgcn_fused<<<dim3((Hh+63)/64, (Nn+127)/128), 256, RGCN_SMEM_BYTES>>>(entIn, p_pre, p_preR, Wr_[0], Wsl_[0], p_h1, p_h1H, rnT);
        fixup_zero<<<32, 256>>>(Wel_[0], entIn, p_h1, p_h1H, zlT, zcT);

        gather_h<<<Nn/2, 256>>>(srcT, (const __half2*)p_h1H, nbT, ebdT);
        rgcn_fused<<<dim3((Hh+63)/64, (Nn+127)/128), 256, RGCN_SMEM_BYTES>>>(p_h1, p_pre, p_preR, Wr_[1], Wsl_[1], p_h2, nullptr, rnT);
        fixup_zero<<<32, 256>>>(Wel_[1], p_h1, p_h2, nullptr, zlT, zcT);

        // entity update: fused sigmoid-gate GEMM with internal row-norm of h2
        tgemm<5><<<dim3(TGX(Hh), TGY(Nn)), 256>>>(entIn, lin_W, entOut, Nn, Hh, Hh, lin_b, p_h2, p_entH);

        float* tmp = entIn; entIn = entOut; entOut = tmp;
    }
    float* entF = entIn;

    const int klen = CH / KSPLIT;   // 1000

    // ---- decoder: fork into two streams ----
    cudaEventRecord(evF, 0);
    cudaStreamWaitEvent(s2, evF, 0);

    // obj branch (stream 0)
    conv_feat<<<Bb, 256>>>(conve_w, conve_b, subj, relI, entF, p_relh, p_featA, 0);
    tgemmH_split<<<dim3(TGX(Hh), TGY(Bb), KSPLIT), 256>>>(p_featA, fce_w, p_partA, Bb, Hh, CH, klen);
    split_reduce_relu<<<(Bb*Hh + 255)/256, 256>>>(p_partA, p_decA, fce_b);
    tgemm<0><<<dim3(TGX(Nn), TGY(Bb)), 256>>>(p_decA, entF, out, Bb, Nn, Hh, nullptr, nullptr, nullptr);

    // rel branch (stream s2)
    conv_feat<<<Bb, 256, 0, s2>>>(convr_w, convr_b, subj, objI, entF, p_relh, p_featB, 1);
    tgemmH_split<<<dim3(TGX(Hh), TGY(Bb), KSPLIT), 256, 0, s2>>>(p_featB, fcr_w, p_partB, Bb, Hh, CH, klen);
    split_reduce_relu<<<(Bb*Hh + 255)/256, 256, 0, s2>>>(p_partB, p_decB, fcr_b);
    tgemm<0><<<dim3(TGX(Rr), TGY(Bb)), 256, 0, s2>>>(p_decB, p_relh, out + (size_t)Bb*Nn, Bb, Rr, Hh, nullptr, nullptr, nullptr);

    cudaEventRecord(evJ, s2);
    cudaStreamWaitEvent(0, evJ, 0);
}

// round 15
// speedup vs baseline: 1.0419x; 1.0419x over previous
#include <cuda_runtime.h>
#include <cuda_fp16.h>
#include <math.h>
#include <stdint.h>

#define Nn 20000
#define Rr 400
#define Hh 200
#define Ee 200000
#define Tt 3
#define Bb 1024
#define Cc 50
#define CH (Cc*Hh)
#define KSPLIT 10
#define NBLK ((Nn + 255) / 256)
#define SLOPEC 0.22916666666666666f
#define EPSN 1e-12f

// ---------------- scratch (device globals; no allocation allowed) ----------------
__device__ float g_ent[Nn*Hh];
__device__ float g_entB[Nn*Hh];
__device__ __half g_entH[Nn*Hh];
__device__ float g_h1[Nn*Hh];
__device__ __half g_h1H[Nn*Hh];
__device__ float g_h2[Nn*Hh];
__device__ float g_pre[Nn*Hh];
__device__ float g_preR[Nn*Hh];
__device__ float g_winv[Nn];
__device__ float g_relh[Rr*Hh];
__device__ float g_x[Rr*2*Hh];
__device__ float g_gi[Rr*3*Hh];
__device__ float g_gh[Rr*3*Hh];
__device__ float g_nrel[Rr*Hh];
// per-timestep (x3) preprocessing buffers
__device__ int   g_relCnt[Tt*Rr];
__device__ int   g_relBase[Tt*(Rr+1)];
__device__ int   g_relCur[Tt*Rr];
__device__ int   g_edgeByRel[Tt*Ee];
__device__ int   g_degCnt[Tt*Nn];
__device__ int   g_nodeBase[Tt*(Nn+1)];
__device__ int   g_nodeCur[Tt*Nn];
__device__ int   g_edgeByDst[Tt*Ee];
__device__ int   g_blkSum[Tt*NBLK];
__device__ int   g_blkOff[Tt*NBLK];
__device__ float g_rnorm[Tt*Nn];
__device__ int   g_zeroList[Tt*Nn];
__device__ int   g_zeroCnt[Tt];
// decoder
__device__ __half g_featA[Bb*CH];
__device__ __half g_featB[Bb*CH];
__device__ float g_decA[Bb*Hh];
__device__ float g_decB[Bb*Hh];
__device__ float g_partA[KSPLIT*Bb*Hh];
__device__ float g_partB[KSPLIT*Bb*Hh];

// ---------------- tf32 helpers ----------------
__device__ __forceinline__ float to_tf32(float x) {
    uint32_t u;
    asm("cvt.rna.tf32.f32 %0, %1;" : "=r"(u) : "r"(__float_as_uint(x)));
    return __uint_as_float(u);
}

__device__ __forceinline__ void mma_tf32(float* d, const uint32_t* a, const uint32_t* b) {
    asm volatile(
        "mma.sync.aligned.m16n8k8.row.col.f32.tf32.tf32.f32 "
        "{%0,%1,%2,%3}, {%4,%5,%6,%7}, {%8,%9}, {%0,%1,%2,%3};\n"
        : "+f"(d[0]), "+f"(d[1]), "+f"(d[2]), "+f"(d[3])
        : "r"(a[0]), "r"(a[1]), "r"(a[2]), "r"(a[3]),
          "r"(b[0]), "r"(b[1]));
}

// predicated 8-float row load into regs
__device__ __forceinline__ void ld_row8(const float* __restrict__ base, int gka, int kmax,
                                        bool ok, float* r) {
    if (ok && gka + 8 <= kmax) {
        float4 v0 = *reinterpret_cast<const float4*>(base + gka);
        float4 v1 = *reinterpret_cast<const float4*>(base + gka + 4);
        r[0]=v0.x; r[1]=v0.y; r[2]=v0.z; r[3]=v0.w;
        r[4]=v1.x; r[5]=v1.y; r[6]=v1.z; r[7]=v1.w;
    } else {
#pragma unroll
        for (int q = 0; q < 8; q++) r[q] = (ok && gka + q < kmax) ? base[gka + q] : 0.f;
    }
}

// predicated 4-float row load into regs
__device__ __forceinline__ void ld_row4(const float* __restrict__ base, int gkw, int kmax,
                                        bool ok, float* r) {
    if (ok && gkw + 4 <= kmax) {
        float4 v = *reinterpret_cast<const float4*>(base + gkw);
        r[0]=v.x; r[1]=v.y; r[2]=v.z; r[3]=v.w;
    } else {
#pragma unroll
        for (int q = 0; q < 4; q++) r[q] = (ok && gkw + q < kmax) ? base[gkw + q] : 0.f;
    }
}

// predicated 8-half row load into regs (as floats)
__device__ __forceinline__ void ld_row8h(const __half* __restrict__ base, int gka, int kmax,
                                         bool ok, float* r) {
    if (ok && gka + 8 <= kmax) {
        uint4 raw = *reinterpret_cast<const uint4*>(base + gka);
        float2 f0 = __half22float2(*reinterpret_cast<__half2*>(&raw.x));
        float2 f1 = __half22float2(*reinterpret_cast<__half2*>(&raw.y));
        float2 f2 = __half22float2(*reinterpret_cast<__half2*>(&raw.z));
        float2 f3 = __half22float2(*reinterpret_cast<__half2*>(&raw.w));
        r[0]=f0.x; r[1]=f0.y; r[2]=f1.x; r[3]=f1.y;
        r[4]=f2.x; r[5]=f2.y; r[6]=f3.x; r[7]=f3.y;
    } else {
#pragma unroll
        for (int q = 0; q < 8; q++) r[q] = (ok && gka + q < kmax) ? __half2float(base[gka + q]) : 0.f;
    }
}

// ---------------- batched (all timesteps) preprocessing ----------------

__global__ void zero_prep3() {
    int tt = blockIdx.y;
    int i = blockIdx.x * blockDim.x + threadIdx.x;
    if (i < Nn) g_degCnt[tt*Nn + i] = 0;
    if (i < Rr) g_relCnt[tt*Rr + i] = 0;
    if (i == 0) g_zeroCnt[tt] = 0;
}

__global__ void hist3(const int* __restrict__ erel_all, const int* __restrict__ dst_all) {
    int tt = blockIdx.y;
    const int* er = erel_all + tt*Ee;
    const int* ds = dst_all + tt*Ee;
    __shared__ int sh[Rr];
    for (int i = threadIdx.x; i < Rr; i += blockDim.x) sh[i] = 0;
    __syncthreads();
    for (int e = blockIdx.x * blockDim.x + threadIdx.x; e < Ee; e += gridDim.x * blockDim.x) {
        atomicAdd(&sh[er[e]], 1);
        atomicAdd(&g_degCnt[tt*Nn + ds[e]], 1);
    }
    __syncthreads();
    for (int i = threadIdx.x; i < Rr; i += blockDim.x)
        if (sh[i]) atomicAdd(&g_relCnt[tt*Rr + i], sh[i]);
}

__global__ void scan_a3() {
    int tt = blockIdx.y;
    int b = blockIdx.x, t = threadIdx.x, i = b*256 + t;
    int v = (i < Nn) ? g_degCnt[tt*Nn + i] : 0;
    int lane = t & 31, w = t >> 5;
    int s = v;
#pragma unroll
    for (int o = 1; o < 32; o <<= 1) {
        int y = __shfl_up_sync(0xffffffffu, s, o);
        if (lane >= o) s += y;
    }
    __shared__ int wsum[8];
    if (lane == 31) wsum[w] = s;
    __syncthreads();
    if (w == 0 && lane < 8) {
        int x = wsum[lane];
#pragma unroll
        for (int o = 1; o < 8; o <<= 1) {
            int y = __shfl_up_sync(0xffu, x, o);
            if (lane >= o) x += y;
        }
        wsum[lane] = x;
    }
    __syncthreads();
    int incl = s + (w > 0 ? wsum[w-1] : 0);
    if (i < Nn) g_nodeBase[tt*(Nn+1) + i] = incl - v;
    if (t == 255) g_blkSum[tt*NBLK + b] = incl;
}

__global__ void scan_mid3() {
    int tt = blockIdx.y;
    __shared__ int sm[512];
    int t = threadIdx.x;
    if (blockIdx.x == 0) {
        int v = (t < NBLK) ? g_blkSum[tt*NBLK + t] : 0;
        sm[t] = v;
        __syncthreads();
        for (int o = 1; o < 512; o <<= 1) {
            int y = (t >= o) ? sm[t-o] : 0;
            __syncthreads();
            sm[t] += y;
            __syncthreads();
        }
        if (t < NBLK) g_blkOff[tt*NBLK + t] = sm[t] - v;
    } else {
        int v = (t < Rr) ? g_relCnt[tt*Rr + t] : 0;
        sm[t] = v;
        __syncthreads();
        for (int o = 1; o < 512; o <<= 1) {
            int y = (t >= o) ? sm[t-o] : 0;
            __syncthreads();
            sm[t] += y;
            __syncthreads();
        }
        if (t < Rr) { int e = sm[t] - v; g_relBase[tt*(Rr+1) + t] = e; g_relCur[tt*Rr + t] = e; }
        if (t == 0) g_relBase[tt*(Rr+1) + Rr] = Ee;
    }
}

__global__ void scan_c3() {
    int tt = blockIdx.y;
    int b = blockIdx.x, i = b*256 + threadIdx.x;
    if (i < Nn) {
        int x = g_nodeBase[tt*(Nn+1) + i] + g_blkOff[tt*NBLK + b];
        g_nodeBase[tt*(Nn+1) + i] = x;
        g_nodeCur[tt*Nn + i] = x;
        int d = g_degCnt[tt*Nn + i];
        g_rnorm[tt*Nn + i] = d > 0 ? 1.0f / (float)d : 0.0f;
        if (d == 0) {
            int k = atomicAdd(&g_zeroCnt[tt], 1);
            g_zeroList[tt*Nn + k] = i;
        }
    }
    if (i == 0) g_nodeBase[tt*(Nn+1) + Nn] = Ee;
}

__global__ void scatter3(const int* __restrict__ erel_all, const int* __restrict__ dst_all) {
    int tt = blockIdx.y;
    const int* er = erel_all + tt*Ee;
    const int* ds = dst_all + tt*Ee;
    int e = blockIdx.x * blockDim.x + threadIdx.x;
    if (e < Ee) {
        int p1 = atomicAdd(&g_relCur[tt*Rr + er[e]], 1);
        g_edgeByRel[tt*Ee + p1] = e;
        int p2 = atomicAdd(&g_nodeCur[tt*Nn + ds[e]], 1);
        g_edgeByDst[tt*Ee + p2] = e;
    }
}

// ---------------- utility kernels ----------------

__global__ void normalize_rows(const float* __restrict__ in, float* __restrict__ out,
                               __half* __restrict__ outH, int rows) {
    int r = blockIdx.x;
    if (r >= rows) return;
    __shared__ float red[256];
    int t = threadIdx.x;
    float v = (t < Hh) ? in[r*Hh + t] : 0.f;
    red[t] = v*v;
    __syncthreads();
    for (int s = 128; s > 0; s >>= 1) { if (t < s) red[t] += red[t+s]; __syncthreads(); }
    float inv = 1.0f / fmaxf(sqrtf(red[0]), EPSN);
    if (t < Hh) {
        float x = v * inv;
        out[r*Hh + t] = x;
        if (outH) outH[r*Hh + t] = __float2half_rn(x);
    }
}

// per-relation mean of entH[src] + build GRU input x
__global__ void rel_mean(const int* __restrict__ srcT, const __half2* __restrict__ entH2,
                         const float* __restrict__ rel_embeds,
                         const int* __restrict__ relBase, const int* __restrict__ edgeByRel) {
    __shared__ int ss[256];
    int r = blockIdx.x, t = threadIdx.x;
    int b0 = relBase[r], b1 = relBase[r+1];
    float2 acc = make_float2(0.f, 0.f);
    for (int cb = b0; cb < b1; cb += 256) {
        int m = min(256, b1 - cb);
        if (t < m) ss[t] = srcT[edgeByRel[cb + t]];
        __syncthreads();
        if (t < Hh/2) {
#pragma unroll 4
            for (int i = 0; i < m; i++) {
                float2 f = __half22float2(entH2[ss[i]*(Hh/2) + t]);
                acc.x += f.x; acc.y += f.y;
            }
        }
        __syncthreads();
    }
    if (t < Hh) g_x[r*2*Hh + t] = rel_embeds[r*Hh + t];
    if (t < Hh/2) {
        int cnt = b1 - b0;
        float invc = cnt > 0 ? 1.0f / (float)cnt : 0.f;
        g_x[r*2*Hh + Hh + 2*t]     = acc.x * invc;
        g_x[r*2*Hh + Hh + 2*t + 1] = acc.y * invc;
    }
}

// GRU gates + l2norm; writes n_rel and relh
__global__ void gru_gate() {
    int r = blockIdx.x, t = threadIdx.x;
    __shared__ float red[256];
    float hp = 0.f;
    if (t < Hh) {
        const float* gi = &g_gi[r*3*Hh];
        const float* gh = &g_gh[r*3*Hh];
        float h  = g_relh[r*Hh + t];
        float rr = 1.f / (1.f + expf(-(gi[t]        + gh[t])));
        float z  = 1.f / (1.f + expf(-(gi[Hh+t]     + gh[Hh+t])));
        float n  = tanhf(gi[2*Hh+t] + rr * gh[2*Hh+t]);
        hp = (1.f - z) * n + z * h;
    }
    red[t] = hp*hp;
    __syncthreads();
    for (int s = 128; s > 0; s >>= 1) { if (t < s) red[t] += red[t+s]; __syncthreads(); }
    float inv = 1.0f / fmaxf(sqrtf(red[0]), EPSN);
    if (t < Hh) {
        float v = hp * inv;
        g_nrel[r*Hh + t] = v;
        g_relh[r*Hh + t] = v;
    }
}

// gather_h: pre[n] = sum over in-edges of hinH[src]
__global__ void gather_h(const int* __restrict__ srcT, const __half2* __restrict__ hinH2,
                         const int* __restrict__ nodeBase, const int* __restrict__ edgeByDst) {
    __shared__ int ss[2][32];
    __shared__ int maxlen;
    int half_id = threadIdx.x >> 7;
    int t = threadIdx.x & 127;
    int n = blockIdx.x * 2 + half_id;
    int b0 = nodeBase[n], b1 = nodeBase[n+1];
    int len = b1 - b0;
    if (threadIdx.x == 0) maxlen = 0;
    __syncthreads();
    if (t == 0) atomicMax(&maxlen, len);
    __syncthreads();
    float2 acc = make_float2(0.f, 0.f);
    int ml = maxlen;
    for (int cb = 0; cb < ml; cb += 32) {
        int m = min(32, len - cb);
        if (t < m) ss[half_id][t] = srcT[edgeByDst[b0 + cb + t]];
        __syncthreads();
        if (t < Hh/2) {
#pragma unroll 4
            for (int i = 0; i < m; i++) {
                float2 h = __half22float2(hinH2[ss[half_id][i]*(Hh/2) + t]);
                acc.x += h.x; acc.y += h.y;
            }
        }
        __syncthreads();
    }
    if (t < Hh/2) ((float2*)g_pre)[n*(Hh/2) + t] = acc;
}

// gather_radd: preR[n] = sum over in-edges of nrel[erel]   (once per step, reused by both layers)
__global__ void gather_radd(const int* __restrict__ erelT,
                            const int* __restrict__ nodeBase, const int* __restrict__ edgeByDst) {
    __shared__ int rs[2][32];
    __shared__ int maxlen;
    int half_id = threadIdx.x >> 7;
    int t = threadIdx.x & 127;
    int n = blockIdx.x * 2 + half_id;
    int b0 = nodeBase[n], b1 = nodeBase[n+1];
    int len = b1 - b0;
    if (threadIdx.x == 0) maxlen = 0;
    __syncthreads();
    if (t == 0) atomicMax(&maxlen, len);
    __syncthreads();
    const float2* nrel2 = (const float2*)g_nrel;
    float2 acc = make_float2(0.f, 0.f);
    int ml = maxlen;
    for (int cb = 0; cb < ml; cb += 32) {
        int m = min(32, len - cb);
        if (t < m) rs[half_id][t] = erelT[edgeByDst[b0 + cb + t]];
        __syncthreads();
        if (t < Hh/2) {
#pragma unroll 4
            for (int i = 0; i < m; i++) {
                float2 r = nrel2[rs[half_id][i]*(Hh/2) + t];
                acc.x += r.x; acc.y += r.y;
            }
        }
        __syncthreads();
    }
    if (t < Hh/2) ((float2*)g_preR)[n*(Hh/2) + t] = acc;
}

// deg==0 rows: out = rrelu(hin @ Wel^T)
__global__ void fixup_zero(const float* __restrict__ Wel, const float* __restrict__ hin,
                           float* __restrict__ hout, __half* __restrict__ houtH,
                           const int* __restrict__ zeroList, const int* __restrict__ zeroCnt) {
    __shared__ float hrow[Hh];
    int zc = *zeroCnt;
    for (int li = blockIdx.x; li < zc; li += gridDim.x) {
        int n = zeroList[li];
        int t = threadIdx.x;
        if (t < Hh) hrow[t] = hin[n*Hh + t];
        __syncthreads();
        if (t < Hh) {
            float s = 0.f;
            for (int k = 0; k < Hh; k++) s += hrow[k] * Wel[t*Hh + k];
            s = s >= 0.f ? s : SLOPEC * s;
            hout[n*Hh + t] = s;
            if (houtH) houtH[n*Hh + t] = __float2half_rn(s);
        }
        __syncthreads();
    }
}

__global__ void rownorm_inv() {
    int row = blockIdx.x * 8 + (threadIdx.x >> 5);
    int lane = threadIdx.x & 31;
    if (row >= Nn) return;
    float s = 0.f;
    for (int c = lane; c < Hh; c += 32) { float v = g_h2[row*Hh + c]; s += v*v; }
    for (int o = 16; o > 0; o >>= 1) s += __shfl_xor_sync(0xffffffff, s, o);
    if (lane == 0) g_winv[row] = 1.0f / fmaxf(sqrtf(s), EPSN);
}

// ---------------- fused RGCN layer (double-buffered, dynamic smem) ----------------
// pre operand = pre[] + preR[]  (h-gather + shared nrel-gather)
#define FPA 136
#define FPW 72
#define RGCN_SMEM_FLOATS (4*16*FPA + 4*16*FPW)
#define RGCN_SMEM_BYTES (RGCN_SMEM_FLOATS * 4)
__global__ void __launch_bounds__(256)
rgcn_fused(const float* __restrict__ hin, const float* __restrict__ pre,
           const float* __restrict__ preR,
           const float* __restrict__ Wr, const float* __restrict__ Wsl,
           float* __restrict__ hout, __half* __restrict__ houtH,
           const float* __restrict__ rnorm) {
    extern __shared__ float dsm[];
    float (*Ah)[16][FPA] = (float(*)[16][FPA])(dsm);
    float (*Ap)[16][FPA] = (float(*)[16][FPA])(dsm + 2*16*FPA);
    float (*Sr)[16][FPW] = (float(*)[16][FPW])(dsm + 4*16*FPA);
    float (*Ss)[16][FPW] = (float(*)[16][FPW])(dsm + 4*16*FPA + 2*16*FPW);

    int tid = threadIdx.x;
    int j0 = blockIdx.x * 64;
    int i0 = blockIdx.y * 128;
    int wid = tid >> 5, lane = tid & 31;
    int wr = wid & 1, wc = wid >> 1;
    int gid = lane >> 2, tig = lane & 3;

    float accR[4][2][4], accS[4][2][4];
#pragma unroll
    for (int a = 0; a < 4; a++)
#pragma unroll
        for (int b = 0; b < 2; b++)
#pragma unroll
            for (int v = 0; v < 4; v++) { accR[a][b][v] = 0.f; accS[a][b][v] = 0.f; }

    int arow = tid >> 1;
    int akoff = (tid & 1) * 8;
    int gr = i0 + arow;
    bool rok = gr < Nn;
    const float* hrow = hin + (size_t)gr * Hh;
    const float* prow = pre + (size_t)gr * Hh;
    const float* qrow = preR + (size_t)gr * Hh;

    int wrow = tid >> 2;
    int wkoff = (tid & 3) * 4;
    int gw = j0 + wrow;
    bool wok = gw < Hh;
    const float* wrp = Wr  + (size_t)gw * Hh;
    const float* wsp = Wsl + (size_t)gw * Hh;

    const int NK = (Hh + 15) / 16;   // 13
    float rh[8], rp[8], rq[8], rr4[4], rs4[4];

    ld_row8(hrow, akoff, Hh, rok, rh);
    ld_row8(prow, akoff, Hh, rok, rp);
    ld_row8(qrow, akoff, Hh, rok, rq);
    ld_row4(wrp, wkoff, Hh, wok, rr4);
    ld_row4(wsp, wkoff, Hh, wok, rs4);
#pragma unroll
    for (int q = 0; q < 8; q++) { Ah[0][akoff+q][arow] = to_tf32(rh[q]); Ap[0][akoff+q][arow] = to_tf32(rp[q] + rq[q]); }
#pragma unroll
    for (int q = 0; q < 4; q++) { Sr[0][wkoff+q][wrow] = to_tf32(rr4[q]); Ss[0][wkoff+q][wrow] = to_tf32(rs4[q]); }
    __syncthreads();

    for (int it = 0; it < NK; it++) {
        int cur = it & 1;
        bool more = (it + 1 < NK);
        if (more) {
            int kt = (it + 1) * 16;
            ld_row8(hrow, kt + akoff, Hh, rok, rh);
            ld_row8(prow, kt + akoff, Hh, rok, rp);
            ld_row8(qrow, kt + akoff, Hh, rok, rq);
            ld_row4(wrp, kt + wkoff, Hh, wok, rr4);
            ld_row4(wsp, kt + wkoff, Hh, wok, rs4);
        }
#pragma unroll
        for (int kk = 0; kk < 16; kk += 8) {
            uint32_t ah[4][4], ap[4][4];
#pragma unroll
            for (int mt = 0; mt < 4; mt++) {
                int r0 = wr*64 + mt*16 + gid;
                ah[mt][0] = __float_as_uint(Ah[cur][kk+tig  ][r0]);
                ah[mt][1] = __float_as_uint(Ah[cur][kk+tig  ][r0+8]);
                ah[mt][2] = __float_as_uint(Ah[cur][kk+tig+4][r0]);
                ah[mt][3] = __float_as_uint(Ah[cur][kk+tig+4][r0+8]);
                ap[mt][0] = __float_as_uint(Ap[cur][kk+tig  ][r0]);
                ap[mt][1] = __float_as_uint(Ap[cur][kk+tig  ][r0+8]);
                ap[mt][2] = __float_as_uint(Ap[cur][kk+tig+4][r0]);
                ap[mt][3] = __float_as_uint(Ap[cur][kk+tig+4][r0+8]);
            }
            uint32_t br[2][2], bs[2][2];
#pragma unroll
            for (int nt = 0; nt < 2; nt++) {
                int cn = wc*16 + nt*8 + gid;
                br[nt][0] = __float_as_uint(Sr[cur][kk+tig  ][cn]);
                br[nt][1] = __float_as_uint(Sr[cur][kk+tig+4][cn]);
                bs[nt][0] = __float_as_uint(Ss[cur][kk+tig  ][cn]);
                bs[nt][1] = __float_as_uint(Ss[cur][kk+tig+4][cn]);
            }
#pragma unroll
            for (int mt = 0; mt < 4; mt++)
#pragma unroll
                for (int nt = 0; nt < 2; nt++) {
                    mma_tf32(accR[mt][nt], ap[mt], br[nt]);
                    mma_tf32(accS[mt][nt], ah[mt], bs[nt]);
                }
        }
        if (more) {
            int nxt = 1 - cur;
#pragma unroll
            for (int q = 0; q < 8; q++) { Ah[nxt][akoff+q][arow] = to_tf32(rh[q]); Ap[nxt][akoff+q][arow] = to_tf32(rp[q] + rq[q]); }
#pragma unroll
            for (int q = 0; q < 4; q++) { Sr[nxt][wkoff+q][wrow] = to_tf32(rr4[q]); Ss[nxt][wkoff+q][wrow] = to_tf32(rs4[q]); }
            __syncthreads();
        }
    }

#pragma unroll
    for (int mt = 0; mt < 4; mt++) {
#pragma unroll
        for (int nt = 0; nt < 2; nt++) {
            int rbase = i0 + wr*64 + mt*16 + gid;
            int cbase = j0 + wc*16 + nt*8 + tig*2;
#pragma unroll
            for (int v = 0; v < 4; v++) {
                int row = rbase + ((v >= 2) ? 8 : 0);
                int col = cbase + (v & 1);
                if (row >= Nn || col >= Hh) continue;
                float x = accR[mt][nt][v] * rnorm[row] + accS[mt][nt][v];
                x = x >= 0.f ? x : SLOPEC * x;
                hout[(size_t)row * Hh + col] = x;
                if (houtH) houtH[(size_t)row * Hh + col] = __float2half_rn(x);
            }
        }
    }
}

// ---------------- tf32 GEMM (fp32 A), double-buffered: C = epi(A @ W^T) ----------------
// EPI: 0 plain | 4 acc+bias | 5 fused gate-update (rowscale = precomputed h2 row-norm inv)
#define TPAD 136
template<int EPI>
__global__ void __launch_bounds__(256)
tgemm(const float* __restrict__ A, const float* __restrict__ W,
      float* __restrict__ C, int M, int Nout, int Kdim,
      const float* __restrict__ bias,
      const float* __restrict__ Sadd,
      const float* __restrict__ rowscale,
      __half* __restrict__ Chalf) {
    __shared__ float As[2][16][TPAD];
    __shared__ float Ws[2][16][TPAD];
    int tid = threadIdx.x;
    int j0 = blockIdx.x * 128;
    int i0 = blockIdx.y * 128;

    int wid = tid >> 5, lane = tid & 31;
    int wr = wid & 1, wc = wid >> 1;
    int gid = lane >> 2, tig = lane & 3;

    float acc[4][4][4];
#pragma unroll
    for (int a = 0; a < 4; a++)
#pragma unroll
        for (int b = 0; b < 4; b++)
#pragma unroll
            for (int v = 0; v < 4; v++) acc[a][b][v] = 0.f;

    int arow = tid >> 1;
    int akoff = (tid & 1) * 8;
    int gr = i0 + arow;
    int gw = j0 + arow;
    bool rok = gr < M;
    bool wok = gw < Nout;
    const float* Arow_p = A + (size_t)gr * Kdim;
    const float* Wrow_p = W + (size_t)gw * Kdim;

    const int NK = (Kdim + 15) / 16;
    float ra[8], rw[8];

    ld_row8(Arow_p, akoff, Kdim, rok, ra);
    ld_row8(Wrow_p, akoff, Kdim, wok, rw);
#pragma unroll
    for (int q = 0; q < 8; q++) { As[0][akoff+q][arow] = to_tf32(ra[q]); Ws[0][akoff+q][arow] = to_tf32(rw[q]); }
    __syncthreads();

    for (int it = 0; it < NK; it++) {
        int cur = it & 1;
        bool more = (it + 1 < NK);
        if (more) {
            int kt = (it + 1) * 16;
            ld_row8(Arow_p, kt + akoff, Kdim, rok, ra);
            ld_row8(Wrow_p, kt + akoff, Kdim, wok, rw);
        }
#pragma unroll
        for (int kk = 0; kk < 16; kk += 8) {
            uint32_t af[4][4];
            uint32_t bf[4][2];
#pragma unroll
            for (int mt = 0; mt < 4; mt++) {
                int r0 = wr*64 + mt*16 + gid;
                af[mt][0] = __float_as_uint(As[cur][kk+tig  ][r0]);
                af[mt][1] = __float_as_uint(As[cur][kk+tig  ][r0+8]);
                af[mt][2] = __float_as_uint(As[cur][kk+tig+4][r0]);
                af[mt][3] = __float_as_uint(As[cur][kk+tig+4][r0+8]);
            }
#pragma unroll
            for (int nt = 0; nt < 4; nt++) {
                int cn = wc*32 + nt*8 + gid;
                bf[nt][0] = __float_as_uint(Ws[cur][kk+tig  ][cn]);
                bf[nt][1] = __float_as_uint(Ws[cur][kk+tig+4][cn]);
            }
#pragma unroll
            for (int mt = 0; mt < 4; mt++)
#pragma unroll
                for (int nt = 0; nt < 4; nt++)
                    mma_tf32(acc[mt][nt], af[mt], bf[nt]);
        }
        if (more) {
            int nxt = 1 - cur;
#pragma unroll
            for (int q = 0; q < 8; q++) { As[nxt][akoff+q][arow] = to_tf32(ra[q]); Ws[nxt][akoff+q][arow] = to_tf32(rw[q]); }
            __syncthreads();
        }
    }

#pragma unroll
    for (int mt = 0; mt < 4; mt++) {
#pragma unroll
        for (int nt = 0; nt < 4; nt++) {
            int rbase = i0 + wr*64 + mt*16 + gid;
            int cbase = j0 + wc*32 + nt*8 + tig*2;
#pragma unroll
            for (int v = 0; v < 4; v++) {
                int row = rbase + ((v >= 2) ? 8 : 0);
                int col = cbase + (v & 1);
                if (row >= M || col >= Nout) continue;
                float x = acc[mt][nt][v];
                if (EPI == 4) {
                    x += bias[col];
                } else if (EPI == 5) {
                    float u = 1.f / (1.f + expf(-(x + bias[col])));
                    float e = A[(size_t)row * Kdim + col];
                    float w = Sadd[(size_t)row * Nout + col] * rowscale[row];
                    x = e + u * (w - e);
                    Chalf[(size_t)row * Nout + col] = __float2half_rn(x);
                }
                C[(size_t)row * Nout + col] = x;
            }
        }
    }
}

// ---------------- split-K GEMM with fp16 A (double-buffered): raw partials ----------------
__global__ void __launch_bounds__(256)
tgemmH_split(const __half* __restrict__ A, const float* __restrict__ W,
             float* __restrict__ C, int M, int Nout, int Kdim, int klen) {
    __shared__ float As[2][16][TPAD];
    __shared__ float Ws[2][16][TPAD];
    int tid = threadIdx.x;
    int j0 = blockIdx.x * 128;
    int i0 = blockIdx.y * 128;
    int k0 = blockIdx.z * klen;
    int k1 = min(Kdim, k0 + klen);

    int wid = tid >> 5, lane = tid & 31;
    int wr = wid & 1, wc = wid >> 1;
    int gid = lane >> 2, tig = lane & 3;

    float acc[4][4][4];
#pragma unroll
    for (int a = 0; a < 4; a++)
#pragma unroll
        for (int b = 0; b < 4; b++)
#pragma unroll
            for (int v = 0; v < 4; v++) acc[a][b][v] = 0.f;

    int arow = tid >> 1;
    int akoff = (tid & 1) * 8;
    int gr = i0 + arow;
    int gw = j0 + arow;
    bool rok = gr < M;
    bool wok = gw < Nout;
    const __half* Arow_p = A + (size_t)gr * Kdim;
    const float* Wrow_p = W + (size_t)gw * Kdim;

    const int NK = (k1 - k0 + 15) / 16;
    float ra[8], rw[8];

    ld_row8h(Arow_p, k0 + akoff, k1, rok, ra);
    ld_row8(Wrow_p, k0 + akoff, k1, wok, rw);
#pragma unroll
    for (int q = 0; q < 8; q++) { As[0][akoff+q][arow] = ra[q]; Ws[0][akoff+q][arow] = to_tf32(rw[q]); }
    __syncthreads();

    for (int it = 0; it < NK; it++) {
        int cur = it & 1;
        bool more = (it + 1 < NK);
        if (more) {
            int kt = k0 + (it + 1) * 16;
            ld_row8h(Arow_p, kt + akoff, k1, rok, ra);
            ld_row8(Wrow_p, kt + akoff, k1, wok, rw);
        }
#pragma unroll
        for (int kk = 0; kk < 16; kk += 8) {
            uint32_t af[4][4];
            uint32_t bf[4][2];
#pragma unroll
            for (int mt = 0; mt < 4; mt++) {
                int r0 = wr*64 + mt*16 + gid;
                af[mt][0] = __float_as_uint(As[cur][kk+tig  ][r0]);
                af[mt][1] = __float_as_uint(As[cur][kk+tig  ][r0+8]);
                af[mt][2] = __float_as_uint(As[cur][kk+tig+4][r0]);
                af[mt][3] = __float_as_uint(As[cur][kk+tig+4][r0+8]);
            }
#pragma unroll
            for (int nt = 0; nt < 4; nt++) {
                int cn = wc*32 + nt*8 + gid;
                bf[nt][0] = __float_as_uint(Ws[cur][kk+tig  ][cn]);
                bf[nt][1] = __float_as_uint(Ws[cur][kk+tig+4][cn]);
            }
#pragma unroll
            for (int mt = 0; mt < 4; mt++)
#pragma unroll
                for (int nt = 0; nt < 4; nt++)
                    mma_tf32(acc[mt][nt], af[mt], bf[nt]);
        }
        if (more) {
            int nxt = 1 - cur;
#pragma unroll
            for (int q = 0; q < 8; q++) { As[nxt][akoff+q][arow] = ra[q]; Ws[nxt][akoff+q][arow] = to_tf32(rw[q]); }
            __syncthreads();
        }
    }

    float* Cb = C + (size_t)blockIdx.z * M * Nout;
#pragma unroll
    for (int mt = 0; mt < 4; mt++) {
#pragma unroll
        for (int nt = 0; nt < 4; nt++) {
            int rbase = i0 + wr*64 + mt*16 + gid;
            int cbase = j0 + wc*32 + nt*8 + tig*2;
#pragma unroll
            for (int v = 0; v < 4; v++) {
                int row = rbase + ((v >= 2) ? 8 : 0);
                int col = cbase + (v & 1);
                if (row >= M || col >= Nout) continue;
                Cb[(size_t)row * Nout + col] = acc[mt][nt][v];
            }
        }
    }
}

// deterministic split-K reduction + bias + relu
__global__ void split_reduce_relu(const float* __restrict__ part, float* __restrict__ dst,
                                  const float* __restrict__ bias) {
    int i = blockIdx.x * blockDim.x + threadIdx.x;
    if (i < Bb*Hh) {
        float s = 0.f;
#pragma unroll
        for (int z = 0; z < KSPLIT; z++) s += part[(size_t)z * Bb * Hh + i];
        s += bias[i % Hh];
        dst[i] = fmaxf(s, 0.f);
    }
}

// ---------------- decoder: fused gather + conv + relu (fp16 feat out) ----------------
__global__ void conv_feat(const float* __restrict__ cw, const float* __restrict__ cb,
                          const int* __restrict__ sidx, const int* __restrict__ oidx,
                          const float* __restrict__ ent, const float* __restrict__ other,
                          __half* __restrict__ feat, int mode) {
    int b = blockIdx.x;
    __shared__ float s1[Hh+2], s2[Hh+2];
    __shared__ float w[Cc*6];
    __shared__ float bb[Cc];
    int t = threadIdx.x;
    if (t < Hh) {
        s1[t+1] = ent[sidx[b]*Hh + t];
        s2[t+1] = mode ? ent[oidx[b]*Hh + t] : other[oidx[b]*Hh + t];
    }
    if (t == 0) { s1[0] = 0.f; s2[0] = 0.f; s1[Hh+1] = 0.f; s2[Hh+1] = 0.f; }
    for (int i = t; i < Cc*6; i += blockDim.x) w[i] = cw[i];
    if (t < Cc) bb[t] = cb[t];
    __syncthreads();
    for (int idx = t; idx < CH; idx += blockDim.x) {
        int c = idx / Hh, i = idx % Hh;
        const float* wc = &w[c*6];
        float v = bb[c]
            + s1[i]*wc[0] + s1[i+1]*wc[1] + s1[i+2]*wc[2]
            + s2[i]*wc[3] + s2[i+1]*wc[4] + s2[i+2]*wc[5];
        feat[(size_t)b*CH + idx] = __float2half_rn(fmaxf(v, 0.f));
    }
}

// ---------------- host ----------------

static void* symaddr(const void* s) { void* p = nullptr; cudaGetSymbolAddress(&p, s); return p; }

extern "C" void kernel_launch(void* const* d_in, const int* in_sizes, int n_in,
                              void* d_out, int out_size) {
    const float* ent_embeds = (const float*)d_in[0];
    const float* rel_embeds = (const float*)d_in[1];
    const float* Wr1  = (const float*)d_in[2];
    const float* Wsl1 = (const float*)d_in[3];
    const float* Wel1 = (const float*)d_in[4];
    const float* Wr2  = (const float*)d_in[5];
    const float* Wsl2 = (const float*)d_in[6];
    const float* Wel2 = (const float*)d_in[7];
    const float* lin_W = (const float*)d_in[8];
    const float* lin_b = (const float*)d_in[9];
    const float* gru_Wih = (const float*)d_in[10];
    const float* gru_Whh = (const float*)d_in[11];
    const float* gru_bih = (const float*)d_in[12];
    const float* gru_bhh = (const float*)d_in[13];
    const float* conve_w = (const float*)d_in[14];
    const float* conve_b = (const float*)d_in[15];
    const float* fce_w = (const float*)d_in[16];
    const float* fce_b = (const float*)d_in[17];
    const float* convr_w = (const float*)d_in[18];
    const float* convr_b = (const float*)d_in[19];
    const float* fcr_w = (const float*)d_in[20];
    const float* fcr_b = (const float*)d_in[21];
    const int* src  = (const int*)d_in[22];
    const int* dst  = (const int*)d_in[23];
    const int* erel = (const int*)d_in[24];
    const int* subj = (const int*)d_in[25];
    const int* relI = (const int*)d_in[26];
    const int* objI = (const int*)d_in[27];
    float* out = (float*)d_out;

    float* p_entA  = (float*)symaddr(g_ent);
    float* p_entB  = (float*)symaddr(g_entB);
    __half* p_entH = (__half*)symaddr(g_entH);
    float* p_h1    = (float*)symaddr(g_h1);
    __half* p_h1H  = (__half*)symaddr(g_h1H);
    float* p_h2    = (float*)symaddr(g_h2);
    float* p_pre   = (float*)symaddr(g_pre);
    float* p_preR  = (float*)symaddr(g_preR);
    float* p_winv  = (float*)symaddr(g_winv);
    float* p_relh  = (float*)symaddr(g_relh);
    float* p_x     = (float*)symaddr(g_x);
    float* p_gi    = (float*)symaddr(g_gi);
    float* p_gh    = (float*)symaddr(g_gh);
    int* p_relBase = (int*)symaddr(g_relBase);
    int* p_edgeByRel = (int*)symaddr(g_edgeByRel);
    int* p_nodeBase = (int*)symaddr(g_nodeBase);
    int* p_edgeByDst = (int*)symaddr(g_edgeByDst);
    float* p_rnorm = (float*)symaddr(g_rnorm);
    int* p_zeroList = (int*)symaddr(g_zeroList);
    int* p_zeroCnt = (int*)symaddr(g_zeroCnt);
    __half* p_featA = (__half*)symaddr(g_featA);
    __half* p_featB = (__half*)symaddr(g_featB);
    float* p_decA  = (float*)symaddr(g_decA);
    float* p_decB  = (float*)symaddr(g_decB);
    float* p_partA = (float*)symaddr(g_partA);
    float* p_partB = (float*)symaddr(g_partB);

    const float* Wr_[2]  = {Wr1, Wr2};
    const float* Wsl_[2] = {Wsl1, Wsl2};
    const float* Wel_[2] = {Wel1, Wel2};

    #define TGX(Nc) (((Nc)+127)/128)
    #define TGY(Mr) (((Mr)+127)/128)

    // One-time stream/event creation + smem attribute (host-side resource
    // init; identical GPU work enqueued every call). Per-call creation
    // allocated device memory during graph capture → harness guard.
    static cudaStream_t sP = nullptr, sR = nullptr, s2 = nullptr;
    static cudaEvent_t evRoot, evPrep, evF, evJ, evE[Tt], evG[Tt];
    if (sP == nullptr) {
        cudaStreamCreate(&sP);
        cudaStreamCreate(&sR);
        cudaStreamCreate(&s2);
        cudaEventCreateWithFlags(&evRoot, cudaEventDisableTiming);
        cudaEventCreateWithFlags(&evPrep, cudaEventDisableTiming);
        cudaEventCreateWithFlags(&evF, cudaEventDisableTiming);
        cudaEventCreateWithFlags(&evJ, cudaEventDisableTiming);
        for (int t = 0; t < Tt; t++) {
            cudaEventCreateWithFlags(&evE[t], cudaEventDisableTiming);
            cudaEventCreateWithFlags(&evG[t], cudaEventDisableTiming);
        }
        cudaFuncSetAttribute(rgcn_fused, cudaFuncAttributeMaxDynamicSharedMemorySize, RGCN_SMEM_BYTES);
    }

    // ---- fork: batched 3-step edge preprocessing on sP ----
    cudaEventRecord(evRoot, 0);
    cudaStreamWaitEvent(sP, evRoot, 0);
    zero_prep3<<<dim3((Nn+255)/256, Tt), 256, 0, sP>>>();
    hist3<<<dim3(160, Tt), 256, 0, sP>>>(erel, dst);
    scan_a3<<<dim3(NBLK, Tt), 256, 0, sP>>>();
    scan_mid3<<<dim3(2, Tt), 512, 0, sP>>>();
    scan_c3<<<dim3(NBLK, Tt), 256, 0, sP>>>();
    scatter3<<<dim3((Ee+255)/256, Tt), 256, 0, sP>>>(erel, dst);
    cudaEventRecord(evPrep, sP);

    // ---- init (stream 0, concurrent with prep) ----
    normalize_rows<<<Nn, 256>>>(ent_embeds, p_entA, p_entH, Nn);
    normalize_rows<<<Rr, 256>>>(rel_embeds, p_relh, nullptr, Rr);
    cudaStreamWaitEvent(0, evPrep, 0);

    float* entIn = p_entA;
    float* entOut = p_entB;

    for (int t = 0; t < Tt; t++) {
        const int* srcT  = src  + t*Ee;
        const int* erelT = erel + t*Ee;
        const int* nbT   = p_nodeBase + t*(Nn+1);
        const int* ebdT  = p_edgeByDst + t*Ee;
        const int* rbT   = p_relBase + t*(Rr+1);
        const int* ebrT  = p_edgeByRel + t*Ee;
        const float* rnT = p_rnorm + t*Nn;
        const int* zlT   = p_zeroList + t*Nn;
        const int* zcT   = p_zeroCnt + t;

        // fork: relation-GRU path + preR gather on sR; big h-gather on stream 0
        cudaEventRecord(evE[t], 0);
        cudaStreamWaitEvent(sR, evE[t], 0);

        gather_h<<<Nn/2, 256>>>(srcT, (const __half2*)p_entH, nbT, ebdT);

        rel_mean<<<Rr, 256, 0, sR>>>(srcT, (const __half2*)p_entH, rel_embeds, rbT, ebrT);
        tgemm<4><<<dim3(TGX(3*Hh), TGY(Rr)), 256, 0, sR>>>(p_x, gru_Wih, p_gi, Rr, 3*Hh, 2*Hh, gru_bih, nullptr, nullptr, nullptr);
        tgemm<4><<<dim3(TGX(3*Hh), TGY(Rr)), 256, 0, sR>>>(p_relh, gru_Whh, p_gh, Rr, 3*Hh, Hh, gru_bhh, nullptr, nullptr, nullptr);
        gru_gate<<<Rr, 256, 0, sR>>>();
        gather_radd<<<Nn/2, 256, 0, sR>>>(erelT, nbT, ebdT);   // preR, reused by BOTH layers
        cudaEventRecord(evG[t], sR);
        cudaStreamWaitEvent(0, evG[t], 0);

        rgcn_fused<<<dim3((Hh+63)/64, (Nn+127)/128), 256, RGCN_SMEM_BYTES>>>(entIn, p_pre, p_preR, Wr_[0], Wsl_[0], p_h1, p_h1H, rnT);
        fixup_zero<<<32, 256>>>(Wel_[0], entIn, p_h1, p_h1H, zlT, zcT);

        gather_h<<<Nn/2, 256>>>(srcT, (const __half2*)p_h1H, nbT, ebdT);
        rgcn_fused<<<dim3((Hh+63)/64, (Nn+127)/128), 256, RGCN_SMEM_BYTES>>>(p_h1, p_pre, p_preR, Wr_[1], Wsl_[1], p_h2, nullptr, rnT);
        fixup_zero<<<32, 256>>>(Wel_[1], p_h1, p_h2, nullptr, zlT, zcT);

        // entity update: parallel row-norm then fused sigmoid-gate GEMM
        rownorm_inv<<<(Nn + 7)/8, 256>>>();
        tgemm<5><<<dim3(TGX(Hh), TGY(Nn)), 256>>>(entIn, lin_W, entOut, Nn, Hh, Hh, lin_b, p_h2, p_winv, p_entH);

        float* tmp = entIn; entIn = entOut; entOut = tmp;
    }
    float* entF = entIn;

    const int klen = CH / KSPLIT;   // 1000

    // ---- decoder: fork into two streams ----
    cudaEventRecord(evF, 0);
    cudaStreamWaitEvent(s2, evF, 0);

    // obj branch (stream 0)
    conv_feat<<<Bb, 256>>>(conve_w, conve_b, subj, relI, entF, p_relh, p_featA, 0);
    tgemmH_split<<<dim3(TGX(Hh), TGY(Bb), KSPLIT), 256>>>(p_featA, fce_w, p_partA, Bb, Hh, CH, klen);
    split_reduce_relu<<<(Bb*Hh + 255)/256, 256>>>(p_partA, p_decA, fce_b);
    tgemm<0><<<dim3(TGX(Nn), TGY(Bb)), 256>>>(p_decA, entF, out, Bb, Nn, Hh, nullptr, nullptr, nullptr, nullptr);

    // rel branch (stream s2)
    conv_feat<<<Bb, 256, 0, s2>>>(convr_w, convr_b, subj, objI, entF, p_relh, p_featB, 1);
    tgemmH_split<<<dim3(TGX(Hh), TGY(Bb), KSPLIT), 256, 0, s2>>>(p_featB, fcr_w, p_partB, Bb, Hh, CH, klen);
    split_reduce_relu<<<(Bb*Hh + 255)/256, 256, 0, s2>>>(p_partB, p_decB, fcr_b);
    tgemm<0><<<dim3(TGX(Rr), TGY(Bb)), 256, 0, s2>>>(p_decB, p_relh, out + (size_t)Bb*Nn, Bb, Rr, Hh, nullptr, nullptr, nullptr, nullptr);

    cudaEventRecord(evJ, s2);
    cudaStreamWaitEvent(0, evJ, 0);
}

// round 16
// speedup vs baseline: 1.0456x; 1.0035x over previous
#include <cuda_runtime.h>
#include <cuda_fp16.h>
#include <math.h>
#include <stdint.h>

#define Nn 20000
#define Rr 400
#define Hh 200
#define Ee 200000
#define Tt 3
#define Bb 1024
#define Cc 50
#define CH (Cc*Hh)
#define KSPLIT 10
#define NBLK ((Nn + 255) / 256)
#define SLOPEC 0.22916666666666666f
#define EPSN 1e-12f

// ---------------- scratch (device globals; no allocation allowed) ----------------
__device__ float g_ent[Nn*Hh];
__device__ float g_entB[Nn*Hh];
__device__ __half g_entH[Nn*Hh];
__device__ float g_h1[Nn*Hh];
__device__ __half g_h1H[Nn*Hh];
__device__ float g_h2[Nn*Hh];
__device__ float g_pre[Nn*Hh];
__device__ float g_preR[Nn*Hh];
__device__ float g_winv[Nn];
__device__ float g_relh[Rr*Hh];
__device__ float g_x[Rr*2*Hh];
__device__ float g_gi[Rr*3*Hh];
__device__ float g_gh[Rr*3*Hh];
__device__ float g_nrel[Rr*Hh];
// per-timestep (x3) preprocessing buffers
__device__ int   g_relCnt[Tt*Rr];
__device__ int   g_relBase[Tt*(Rr+1)];
__device__ int   g_relCur[Tt*Rr];
__device__ int   g_edgeByRel[Tt*Ee];
__device__ int   g_degCnt[Tt*Nn];
__device__ int   g_nodeBase[Tt*(Nn+1)];
__device__ int   g_nodeCur[Tt*Nn];
__device__ int   g_edgeByDst[Tt*Ee];
__device__ int   g_blkSum[Tt*NBLK];
__device__ int   g_blkOff[Tt*NBLK];
__device__ float g_rnorm[Tt*Nn];
__device__ int   g_zeroList[Tt*Nn];
__device__ int   g_zeroCnt[Tt];
// decoder
__device__ __half g_featA[Bb*CH];
__device__ __half g_featB[Bb*CH];
__device__ float g_decA[Bb*Hh];
__device__ float g_decB[Bb*Hh];
__device__ float g_partA[KSPLIT*Bb*Hh];
__device__ float g_partB[KSPLIT*Bb*Hh];

// ---------------- tf32 helpers ----------------
__device__ __forceinline__ float to_tf32(float x) {
    uint32_t u;
    asm("cvt.rna.tf32.f32 %0, %1;" : "=r"(u) : "r"(__float_as_uint(x)));
    return __uint_as_float(u);
}

__device__ __forceinline__ void mma_tf32(float* d, const uint32_t* a, const uint32_t* b) {
    asm volatile(
        "mma.sync.aligned.m16n8k8.row.col.f32.tf32.tf32.f32 "
        "{%0,%1,%2,%3}, {%4,%5,%6,%7}, {%8,%9}, {%0,%1,%2,%3};\n"
        : "+f"(d[0]), "+f"(d[1]), "+f"(d[2]), "+f"(d[3])
        : "r"(a[0]), "r"(a[1]), "r"(a[2]), "r"(a[3]),
          "r"(b[0]), "r"(b[1]));
}

// predicated 8-float row load into regs
__device__ __forceinline__ void ld_row8(const float* __restrict__ base, int gka, int kmax,
                                        bool ok, float* r) {
    if (ok && gka + 8 <= kmax) {
        float4 v0 = *reinterpret_cast<const float4*>(base + gka);
        float4 v1 = *reinterpret_cast<const float4*>(base + gka + 4);
        r[0]=v0.x; r[1]=v0.y; r[2]=v0.z; r[3]=v0.w;
        r[4]=v1.x; r[5]=v1.y; r[6]=v1.z; r[7]=v1.w;
    } else {
#pragma unroll
        for (int q = 0; q < 8; q++) r[q] = (ok && gka + q < kmax) ? base[gka + q] : 0.f;
    }
}

// predicated 4-float row load into regs
__device__ __forceinline__ void ld_row4(const float* __restrict__ base, int gkw, int kmax,
                                        bool ok, float* r) {
    if (ok && gkw + 4 <= kmax) {
        float4 v = *reinterpret_cast<const float4*>(base + gkw);
        r[0]=v.x; r[1]=v.y; r[2]=v.z; r[3]=v.w;
    } else {
#pragma unroll
        for (int q = 0; q < 4; q++) r[q] = (ok && gkw + q < kmax) ? base[gkw + q] : 0.f;
    }
}

// predicated 8-half row load into regs (as floats)
__device__ __forceinline__ void ld_row8h(const __half* __restrict__ base, int gka, int kmax,
                                         bool ok, float* r) {
    if (ok && gka + 8 <= kmax) {
        uint4 raw = *reinterpret_cast<const uint4*>(base + gka);
        float2 f0 = __half22float2(*reinterpret_cast<__half2*>(&raw.x));
        float2 f1 = __half22float2(*reinterpret_cast<__half2*>(&raw.y));
        float2 f2 = __half22float2(*reinterpret_cast<__half2*>(&raw.z));
        float2 f3 = __half22float2(*reinterpret_cast<__half2*>(&raw.w));
        r[0]=f0.x; r[1]=f0.y; r[2]=f1.x; r[3]=f1.y;
        r[4]=f2.x; r[5]=f2.y; r[6]=f3.x; r[7]=f3.y;
    } else {
#pragma unroll
        for (int q = 0; q < 8; q++) r[q] = (ok && gka + q < kmax) ? __half2float(base[gka + q]) : 0.f;
    }
}

// ---------------- batched (all timesteps) preprocessing ----------------

__global__ void zero_prep3() {
    int tt = blockIdx.y;
    int i = blockIdx.x * blockDim.x + threadIdx.x;
    if (i < Nn) g_degCnt[tt*Nn + i] = 0;
    if (i < Rr) g_relCnt[tt*Rr + i] = 0;
    if (i == 0) g_zeroCnt[tt] = 0;
}

__global__ void hist3(const int* __restrict__ erel_all, const int* __restrict__ dst_all) {
    int tt = blockIdx.y;
    const int* er = erel_all + tt*Ee;
    const int* ds = dst_all + tt*Ee;
    __shared__ int sh[Rr];
    for (int i = threadIdx.x; i < Rr; i += blockDim.x) sh[i] = 0;
    __syncthreads();
    for (int e = blockIdx.x * blockDim.x + threadIdx.x; e < Ee; e += gridDim.x * blockDim.x) {
        atomicAdd(&sh[er[e]], 1);
        atomicAdd(&g_degCnt[tt*Nn + ds[e]], 1);
    }
    __syncthreads();
    for (int i = threadIdx.x; i < Rr; i += blockDim.x)
        if (sh[i]) atomicAdd(&g_relCnt[tt*Rr + i], sh[i]);
}

__global__ void scan_a3() {
    int tt = blockIdx.y;
    int b = blockIdx.x, t = threadIdx.x, i = b*256 + t;
    int v = (i < Nn) ? g_degCnt[tt*Nn + i] : 0;
    int lane = t & 31, w = t >> 5;
    int s = v;
#pragma unroll
    for (int o = 1; o < 32; o <<= 1) {
        int y = __shfl_up_sync(0xffffffffu, s, o);
        if (lane >= o) s += y;
    }
    __shared__ int wsum[8];
    if (lane == 31) wsum[w] = s;
    __syncthreads();
    if (w == 0 && lane < 8) {
        int x = wsum[lane];
#pragma unroll
        for (int o = 1; o < 8; o <<= 1) {
            int y = __shfl_up_sync(0xffu, x, o);
            if (lane >= o) x += y;
        }
        wsum[lane] = x;
    }
    __syncthreads();
    int incl = s + (w > 0 ? wsum[w-1] : 0);
    if (i < Nn) g_nodeBase[tt*(Nn+1) + i] = incl - v;
    if (t == 255) g_blkSum[tt*NBLK + b] = incl;
}

__global__ void scan_mid3() {
    int tt = blockIdx.y;
    __shared__ int sm[512];
    int t = threadIdx.x;
    if (blockIdx.x == 0) {
        int v = (t < NBLK) ? g_blkSum[tt*NBLK + t] : 0;
        sm[t] = v;
        __syncthreads();
        for (int o = 1; o < 512; o <<= 1) {
            int y = (t >= o) ? sm[t-o] : 0;
            __syncthreads();
            sm[t] += y;
            __syncthreads();
        }
        if (t < NBLK) g_blkOff[tt*NBLK + t] = sm[t] - v;
    } else {
        int v = (t < Rr) ? g_relCnt[tt*Rr + t] : 0;
        sm[t] = v;
        __syncthreads();
        for (int o = 1; o < 512; o <<= 1) {
            int y = (t >= o) ? sm[t-o] : 0;
            __syncthreads();
            sm[t] += y;
            __syncthreads();
        }
        if (t < Rr) { int e = sm[t] - v; g_relBase[tt*(Rr+1) + t] = e; g_relCur[tt*Rr + t] = e; }
        if (t == 0) g_relBase[tt*(Rr+1) + Rr] = Ee;
    }
}

__global__ void scan_c3() {
    int tt = blockIdx.y;
    int b = blockIdx.x, i = b*256 + threadIdx.x;
    if (i < Nn) {
        int x = g_nodeBase[tt*(Nn+1) + i] + g_blkOff[tt*NBLK + b];
        g_nodeBase[tt*(Nn+1) + i] = x;
        g_nodeCur[tt*Nn + i] = x;
        int d = g_degCnt[tt*Nn + i];
        g_rnorm[tt*Nn + i] = d > 0 ? 1.0f / (float)d : 0.0f;
        if (d == 0) {
            int k = atomicAdd(&g_zeroCnt[tt], 1);
            g_zeroList[tt*Nn + k] = i;
        }
    }
    if (i == 0) g_nodeBase[tt*(Nn+1) + Nn] = Ee;
}

__global__ void scatter3(const int* __restrict__ erel_all, const int* __restrict__ dst_all) {
    int tt = blockIdx.y;
    const int* er = erel_all + tt*Ee;
    const int* ds = dst_all + tt*Ee;
    int e = blockIdx.x * blockDim.x + threadIdx.x;
    if (e < Ee) {
        int p1 = atomicAdd(&g_relCur[tt*Rr + er[e]], 1);
        g_edgeByRel[tt*Ee + p1] = e;
        int p2 = atomicAdd(&g_nodeCur[tt*Nn + ds[e]], 1);
        g_edgeByDst[tt*Ee + p2] = e;
    }
}

// ---------------- utility kernels ----------------

__global__ void normalize_rows(const float* __restrict__ in, float* __restrict__ out,
                               __half* __restrict__ outH, int rows) {
    int r = blockIdx.x;
    if (r >= rows) return;
    __shared__ float red[256];
    int t = threadIdx.x;
    float v = (t < Hh) ? in[r*Hh + t] : 0.f;
    red[t] = v*v;
    __syncthreads();
    for (int s = 128; s > 0; s >>= 1) { if (t < s) red[t] += red[t+s]; __syncthreads(); }
    float inv = 1.0f / fmaxf(sqrtf(red[0]), EPSN);
    if (t < Hh) {
        float x = v * inv;
        out[r*Hh + t] = x;
        if (outH) outH[r*Hh + t] = __float2half_rn(x);
    }
}

// per-relation mean of entH[src] + build GRU input x
__global__ void rel_mean(const int* __restrict__ srcT, const __half2* __restrict__ entH2,
                         const float* __restrict__ rel_embeds,
                         const int* __restrict__ relBase, const int* __restrict__ edgeByRel) {
    __shared__ int ss[256];
    int r = blockIdx.x, t = threadIdx.x;
    int b0 = relBase[r], b1 = relBase[r+1];
    float2 acc = make_float2(0.f, 0.f);
    for (int cb = b0; cb < b1; cb += 256) {
        int m = min(256, b1 - cb);
        if (t < m) ss[t] = srcT[edgeByRel[cb + t]];
        __syncthreads();
        if (t < Hh/2) {
#pragma unroll 4
            for (int i = 0; i < m; i++) {
                float2 f = __half22float2(entH2[ss[i]*(Hh/2) + t]);
                acc.x += f.x; acc.y += f.y;
            }
        }
        __syncthreads();
    }
    if (t < Hh) g_x[r*2*Hh + t] = rel_embeds[r*Hh + t];
    if (t < Hh/2) {
        int cnt = b1 - b0;
        float invc = cnt > 0 ? 1.0f / (float)cnt : 0.f;
        g_x[r*2*Hh + Hh + 2*t]     = acc.x * invc;
        g_x[r*2*Hh + Hh + 2*t + 1] = acc.y * invc;
    }
}

// GRU gates + l2norm; writes n_rel and relh
__global__ void gru_gate() {
    int r = blockIdx.x, t = threadIdx.x;
    __shared__ float red[256];
    float hp = 0.f;
    if (t < Hh) {
        const float* gi = &g_gi[r*3*Hh];
        const float* gh = &g_gh[r*3*Hh];
        float h  = g_relh[r*Hh + t];
        float rr = 1.f / (1.f + expf(-(gi[t]        + gh[t])));
        float z  = 1.f / (1.f + expf(-(gi[Hh+t]     + gh[Hh+t])));
        float n  = tanhf(gi[2*Hh+t] + rr * gh[2*Hh+t]);
        hp = (1.f - z) * n + z * h;
    }
    red[t] = hp*hp;
    __syncthreads();
    for (int s = 128; s > 0; s >>= 1) { if (t < s) red[t] += red[t+s]; __syncthreads(); }
    float inv = 1.0f / fmaxf(sqrtf(red[0]), EPSN);
    if (t < Hh) {
        float v = hp * inv;
        g_nrel[r*Hh + t] = v;
        g_relh[r*Hh + t] = v;
    }
}

// gather_h: pre[n] = sum over in-edges of hinH[src]
__global__ void gather_h(const int* __restrict__ srcT, const __half2* __restrict__ hinH2,
                         const int* __restrict__ nodeBase, const int* __restrict__ edgeByDst) {
    __shared__ int ss[2][32];
    __shared__ int maxlen;
    int half_id = threadIdx.x >> 7;
    int t = threadIdx.x & 127;
    int n = blockIdx.x * 2 + half_id;
    int b0 = nodeBase[n], b1 = nodeBase[n+1];
    int len = b1 - b0;
    if (threadIdx.x == 0) maxlen = 0;
    __syncthreads();
    if (t == 0) atomicMax(&maxlen, len);
    __syncthreads();
    float2 acc = make_float2(0.f, 0.f);
    int ml = maxlen;
    for (int cb = 0; cb < ml; cb += 32) {
        int m = min(32, len - cb);
        if (t < m) ss[half_id][t] = srcT[edgeByDst[b0 + cb + t]];
        __syncthreads();
        if (t < Hh/2) {
#pragma unroll 4
            for (int i = 0; i < m; i++) {
                float2 h = __half22float2(hinH2[ss[half_id][i]*(Hh/2) + t]);
                acc.x += h.x; acc.y += h.y;
            }
        }
        __syncthreads();
    }
    if (t < Hh/2) ((float2*)g_pre)[n*(Hh/2) + t] = acc;
}

// gather_radd: preR[n] = sum over in-edges of nrel[erel]   (once per step, reused by both layers)
__global__ void gather_radd(const int* __restrict__ erelT,
                            const int* __restrict__ nodeBase, const int* __restrict__ edgeByDst) {
    __shared__ int rs[2][32];
    __shared__ int maxlen;
    int half_id = threadIdx.x >> 7;
    int t = threadIdx.x & 127;
    int n = blockIdx.x * 2 + half_id;
    int b0 = nodeBase[n], b1 = nodeBase[n+1];
    int len = b1 - b0;
    if (threadIdx.x == 0) maxlen = 0;
    __syncthreads();
    if (t == 0) atomicMax(&maxlen, len);
    __syncthreads();
    const float2* nrel2 = (const float2*)g_nrel;
    float2 acc = make_float2(0.f, 0.f);
    int ml = maxlen;
    for (int cb = 0; cb < ml; cb += 32) {
        int m = min(32, len - cb);
        if (t < m) rs[half_id][t] = erelT[edgeByDst[b0 + cb + t]];
        __syncthreads();
        if (t < Hh/2) {
#pragma unroll 4
            for (int i = 0; i < m; i++) {
                float2 r = nrel2[rs[half_id][i]*(Hh/2) + t];
                acc.x += r.x; acc.y += r.y;
            }
        }
        __syncthreads();
    }
    if (t < Hh/2) ((float2*)g_preR)[n*(Hh/2) + t] = acc;
}

// deg==0 rows: out = rrelu(hin @ Wel^T)
__global__ void fixup_zero(const float* __restrict__ Wel, const float* __restrict__ hin,
                           float* __restrict__ hout, __half* __restrict__ houtH,
                           const int* __restrict__ zeroList, const int* __restrict__ zeroCnt) {
    __shared__ float hrow[Hh];
    int zc = *zeroCnt;
    for (int li = blockIdx.x; li < zc; li += gridDim.x) {
        int n = zeroList[li];
        int t = threadIdx.x;
        if (t < Hh) hrow[t] = hin[n*Hh + t];
        __syncthreads();
        if (t < Hh) {
            float s = 0.f;
            for (int k = 0; k < Hh; k++) s += hrow[k] * Wel[t*Hh + k];
            s = s >= 0.f ? s : SLOPEC * s;
            hout[n*Hh + t] = s;
            if (houtH) houtH[n*Hh + t] = __float2half_rn(s);
        }
        __syncthreads();
    }
}

__global__ void rownorm_inv() {
    int row = blockIdx.x * 8 + (threadIdx.x >> 5);
    int lane = threadIdx.x & 31;
    if (row >= Nn) return;
    float s = 0.f;
    for (int c = lane; c < Hh; c += 32) { float v = g_h2[row*Hh + c]; s += v*v; }
    for (int o = 16; o > 0; o >>= 1) s += __shfl_xor_sync(0xffffffff, s, o);
    if (lane == 0) g_winv[row] = 1.0f / fmaxf(sqrtf(s), EPSN);
}

// ---------------- fused RGCN layer (double-buffered, dynamic smem) ----------------
// pre operand = pre[] + preR[]  (h-gather + shared nrel-gather)
#define FPA 136
#define FPW 72
#define RGCN_SMEM_FLOATS (4*16*FPA + 4*16*FPW)
#define RGCN_SMEM_BYTES (RGCN_SMEM_FLOATS * 4)
__global__ void __launch_bounds__(256)
rgcn_fused(const float* __restrict__ hin, const float* __restrict__ pre,
           const float* __restrict__ preR,
           const float* __restrict__ Wr, const float* __restrict__ Wsl,
           float* __restrict__ hout, __half* __restrict__ houtH,
           const float* __restrict__ rnorm) {
    extern __shared__ float dsm[];
    float (*Ah)[16][FPA] = (float(*)[16][FPA])(dsm);
    float (*Ap)[16][FPA] = (float(*)[16][FPA])(dsm + 2*16*FPA);
    float (*Sr)[16][FPW] = (float(*)[16][FPW])(dsm + 4*16*FPA);
    float (*Ss)[16][FPW] = (float(*)[16][FPW])(dsm + 4*16*FPA + 2*16*FPW);

    int tid = threadIdx.x;
    int j0 = blockIdx.x * 64;
    int i0 = blockIdx.y * 128;
    int wid = tid >> 5, lane = tid & 31;
    int wr = wid & 1, wc = wid >> 1;
    int gid = lane >> 2, tig = lane & 3;

    float accR[4][2][4], accS[4][2][4];
#pragma unroll
    for (int a = 0; a < 4; a++)
#pragma unroll
        for (int b = 0; b < 2; b++)
#pragma unroll
            for (int v = 0; v < 4; v++) { accR[a][b][v] = 0.f; accS[a][b][v] = 0.f; }

    int arow = tid >> 1;
    int akoff = (tid & 1) * 8;
    int gr = i0 + arow;
    bool rok = gr < Nn;
    const float* hrow = hin + (size_t)gr * Hh;
    const float* prow = pre + (size_t)gr * Hh;
    const float* qrow = preR + (size_t)gr * Hh;

    int wrow = tid >> 2;
    int wkoff = (tid & 3) * 4;
    int gw = j0 + wrow;
    bool wok = gw < Hh;
    const float* wrp = Wr  + (size_t)gw * Hh;
    const float* wsp = Wsl + (size_t)gw * Hh;

    const int NK = (Hh + 15) / 16;   // 13
    float rh[8], rp[8], rq[8], rr4[4], rs4[4];

    ld_row8(hrow, akoff, Hh, rok, rh);
    ld_row8(prow, akoff, Hh, rok, rp);
    ld_row8(qrow, akoff, Hh, rok, rq);
    ld_row4(wrp, wkoff, Hh, wok, rr4);
    ld_row4(wsp, wkoff, Hh, wok, rs4);
#pragma unroll
    for (int q = 0; q < 8; q++) { Ah[0][akoff+q][arow] = to_tf32(rh[q]); Ap[0][akoff+q][arow] = to_tf32(rp[q] + rq[q]); }
#pragma unroll
    for (int q = 0; q < 4; q++) { Sr[0][wkoff+q][wrow] = to_tf32(rr4[q]); Ss[0][wkoff+q][wrow] = to_tf32(rs4[q]); }
    __syncthreads();

    for (int it = 0; it < NK; it++) {
        int cur = it & 1;
        bool more = (it + 1 < NK);
        if (more) {
            int kt = (it + 1) * 16;
            ld_row8(hrow, kt + akoff, Hh, rok, rh);
            ld_row8(prow, kt + akoff, Hh, rok, rp);
            ld_row8(qrow, kt + akoff, Hh, rok, rq);
            ld_row4(wrp, kt + wkoff, Hh, wok, rr4);
            ld_row4(wsp, kt + wkoff, Hh, wok, rs4);
        }
#pragma unroll
        for (int kk = 0; kk < 16; kk += 8) {
            uint32_t ah[4][4], ap[4][4];
#pragma unroll
            for (int mt = 0; mt < 4; mt++) {
                int r0 = wr*64 + mt*16 + gid;
                ah[mt][0] = __float_as_uint(Ah[cur][kk+tig  ][r0]);
                ah[mt][1] = __float_as_uint(Ah[cur][kk+tig  ][r0+8]);
                ah[mt][2] = __float_as_uint(Ah[cur][kk+tig+4][r0]);
                ah[mt][3] = __float_as_uint(Ah[cur][kk+tig+4][r0+8]);
                ap[mt][0] = __float_as_uint(Ap[cur][kk+tig  ][r0]);
                ap[mt][1] = __float_as_uint(Ap[cur][kk+tig  ][r0+8]);
                ap[mt][2] = __float_as_uint(Ap[cur][kk+tig+4][r0]);
                ap[mt][3] = __float_as_uint(Ap[cur][kk+tig+4][r0+8]);
            }
            uint32_t br[2][2], bs[2][2];
#pragma unroll
            for (int nt = 0; nt < 2; nt++) {
                int cn = wc*16 + nt*8 + gid;
                br[nt][0] = __float_as_uint(Sr[cur][kk+tig  ][cn]);
                br[nt][1] = __float_as_uint(Sr[cur][kk+tig+4][cn]);
                bs[nt][0] = __float_as_uint(Ss[cur][kk+tig  ][cn]);
                bs[nt][1] = __float_as_uint(Ss[cur][kk+tig+4][cn]);
            }
#pragma unroll
            for (int mt = 0; mt < 4; mt++)
#pragma unroll
                for (int nt = 0; nt < 2; nt++) {
                    mma_tf32(accR[mt][nt], ap[mt], br[nt]);
                    mma_tf32(accS[mt][nt], ah[mt], bs[nt]);
                }
        }
        if (more) {
            int nxt = 1 - cur;
#pragma unroll
            for (int q = 0; q < 8; q++) { Ah[nxt][akoff+q][arow] = to_tf32(rh[q]); Ap[nxt][akoff+q][arow] = to_tf32(rp[q] + rq[q]); }
#pragma unroll
            for (int q = 0; q < 4; q++) { Sr[nxt][wkoff+q][wrow] = to_tf32(rr4[q]); Ss[nxt][wkoff+q][wrow] = to_tf32(rs4[q]); }
            __syncthreads();
        }
    }

#pragma unroll
    for (int mt = 0; mt < 4; mt++) {
#pragma unroll
        for (int nt = 0; nt < 2; nt++) {
            int rbase = i0 + wr*64 + mt*16 + gid;
            int cbase = j0 + wc*16 + nt*8 + tig*2;
#pragma unroll
            for (int v = 0; v < 4; v++) {
                int row = rbase + ((v >= 2) ? 8 : 0);
                int col = cbase + (v & 1);
                if (row >= Nn || col >= Hh) continue;
                float x = accR[mt][nt][v] * rnorm[row] + accS[mt][nt][v];
                x = x >= 0.f ? x : SLOPEC * x;
                hout[(size_t)row * Hh + col] = x;
                if (houtH) houtH[(size_t)row * Hh + col] = __float2half_rn(x);
            }
        }
    }
}

// ---------------- tf32 GEMM (fp32 A), double-buffered: C = epi(A @ W^T) ----------------
// EPI: 0 plain | 4 acc+bias | 5 fused gate-update (rowscale = precomputed h2 row-norm inv)
#define TPAD 136
template<int EPI>
__global__ void __launch_bounds__(256)
tgemm(const float* __restrict__ A, const float* __restrict__ W,
      float* __restrict__ C, int M, int Nout, int Kdim,
      const float* __restrict__ bias,
      const float* __restrict__ Sadd,
      const float* __restrict__ rowscale,
      __half* __restrict__ Chalf) {
    __shared__ float As[2][16][TPAD];
    __shared__ float Ws[2][16][TPAD];
    int tid = threadIdx.x;
    int j0 = blockIdx.x * 128;
    int i0 = blockIdx.y * 128;

    int wid = tid >> 5, lane = tid & 31;
    int wr = wid & 1, wc = wid >> 1;
    int gid = lane >> 2, tig = lane & 3;

    float acc[4][4][4];
#pragma unroll
    for (int a = 0; a < 4; a++)
#pragma unroll
        for (int b = 0; b < 4; b++)
#pragma unroll
            for (int v = 0; v < 4; v++) acc[a][b][v] = 0.f;

    int arow = tid >> 1;
    int akoff = (tid & 1) * 8;
    int gr = i0 + arow;
    int gw = j0 + arow;
    bool rok = gr < M;
    bool wok = gw < Nout;
    const float* Arow_p = A + (size_t)gr * Kdim;
    const float* Wrow_p = W + (size_t)gw * Kdim;

    const int NK = (Kdim + 15) / 16;
    float ra[8], rw[8];

    ld_row8(Arow_p, akoff, Kdim, rok, ra);
    ld_row8(Wrow_p, akoff, Kdim, wok, rw);
#pragma unroll
    for (int q = 0; q < 8; q++) { As[0][akoff+q][arow] = to_tf32(ra[q]); Ws[0][akoff+q][arow] = to_tf32(rw[q]); }
    __syncthreads();

    for (int it = 0; it < NK; it++) {
        int cur = it & 1;
        bool more = (it + 1 < NK);
        if (more) {
            int kt = (it + 1) * 16;
            ld_row8(Arow_p, kt + akoff, Kdim, rok, ra);
            ld_row8(Wrow_p, kt + akoff, Kdim, wok, rw);
        }
#pragma unroll
        for (int kk = 0; kk < 16; kk += 8) {
            uint32_t af[4][4];
            uint32_t bf[4][2];
#pragma unroll
            for (int mt = 0; mt < 4; mt++) {
                int r0 = wr*64 + mt*16 + gid;
                af[mt][0] = __float_as_uint(As[cur][kk+tig  ][r0]);
                af[mt][1] = __float_as_uint(As[cur][kk+tig  ][r0+8]);
                af[mt][2] = __float_as_uint(As[cur][kk+tig+4][r0]);
                af[mt][3] = __float_as_uint(As[cur][kk+tig+4][r0+8]);
            }
#pragma unroll
            for (int nt = 0; nt < 4; nt++) {
                int cn = wc*32 + nt*8 + gid;
                bf[nt][0] = __float_as_uint(Ws[cur][kk+tig  ][cn]);
                bf[nt][1] = __float_as_uint(Ws[cur][kk+tig+4][cn]);
            }
#pragma unroll
            for (int mt = 0; mt < 4; mt++)
#pragma unroll
                for (int nt = 0; nt < 4; nt++)
                    mma_tf32(acc[mt][nt], af[mt], bf[nt]);
        }
        if (more) {
            int nxt = 1 - cur;
#pragma unroll
            for (int q = 0; q < 8; q++) { As[nxt][akoff+q][arow] = to_tf32(ra[q]); Ws[nxt][akoff+q][arow] = to_tf32(rw[q]); }
            __syncthreads();
        }
    }

#pragma unroll
    for (int mt = 0; mt < 4; mt++) {
#pragma unroll
        for (int nt = 0; nt < 4; nt++) {
            int rbase = i0 + wr*64 + mt*16 + gid;
            int cbase = j0 + wc*32 + nt*8 + tig*2;
#pragma unroll
            for (int v = 0; v < 4; v++) {
                int row = rbase + ((v >= 2) ? 8 : 0);
                int col = cbase + (v & 1);
                if (row >= M || col >= Nout) continue;
                float x = acc[mt][nt][v];
                if (EPI == 4) {
                    x += bias[col];
                } else if (EPI == 5) {
                    float u = 1.f / (1.f + expf(-(x + bias[col])));
                    float e = A[(size_t)row * Kdim + col];
                    float w = Sadd[(size_t)row * Nout + col] * rowscale[row];
                    x = e + u * (w - e);
                    Chalf[(size_t)row * Nout + col] = __float2half_rn(x);
                }
                C[(size_t)row * Nout + col] = x;
            }
        }
    }
}

// ---------------- split-K GEMM with fp16 A (double-buffered): raw partials ----------------
__global__ void __launch_bounds__(256)
tgemmH_split(const __half* __restrict__ A, const float* __restrict__ W,
             float* __restrict__ C, int M, int Nout, int Kdim, int klen) {
    __shared__ float As[2][16][TPAD];
    __shared__ float Ws[2][16][TPAD];
    int tid = threadIdx.x;
    int j0 = blockIdx.x * 128;
    int i0 = blockIdx.y * 128;
    int k0 = blockIdx.z * klen;
    int k1 = min(Kdim, k0 + klen);

    int wid = tid >> 5, lane = tid & 31;
    int wr = wid & 1, wc = wid >> 1;
    int gid = lane >> 2, tig = lane & 3;

    float acc[4][4][4];
#pragma unroll
    for (int a = 0; a < 4; a++)
#pragma unroll
        for (int b = 0; b < 4; b++)
#pragma unroll
            for (int v = 0; v < 4; v++) acc[a][b][v] = 0.f;

    int arow = tid >> 1;
    int akoff = (tid & 1) * 8;
    int gr = i0 + arow;
    int gw = j0 + arow;
    bool rok = gr < M;
    bool wok = gw < Nout;
    const __half* Arow_p = A + (size_t)gr * Kdim;
    const float* Wrow_p = W + (size_t)gw * Kdim;

    const int NK = (k1 - k0 + 15) / 16;
    float ra[8], rw[8];

    ld_row8h(Arow_p, k0 + akoff, k1, rok, ra);
    ld_row8(Wrow_p, k0 + akoff, k1, wok, rw);
#pragma unroll
    for (int q = 0; q < 8; q++) { As[0][akoff+q][arow] = ra[q]; Ws[0][akoff+q][arow] = to_tf32(rw[q]); }
    __syncthreads();

    for (int it = 0; it < NK; it++) {
        int cur = it & 1;
        bool more = (it + 1 < NK);
        if (more) {
            int kt = k0 + (it + 1) * 16;
            ld_row8h(Arow_p, kt + akoff, k1, rok, ra);
            ld_row8(Wrow_p, kt + akoff, k1, wok, rw);
        }
#pragma unroll
        for (int kk = 0; kk < 16; kk += 8) {
            uint32_t af[4][4];
            uint32_t bf[4][2];
#pragma unroll
            for (int mt = 0; mt < 4; mt++) {
                int r0 = wr*64 + mt*16 + gid;
                af[mt][0] = __float_as_uint(As[cur][kk+tig  ][r0]);
                af[mt][1] = __float_as_uint(As[cur][kk+tig  ][r0+8]);
                af[mt][2] = __float_as_uint(As[cur][kk+tig+4][r0]);
                af[mt][3] = __float_as_uint(As[cur][kk+tig+4][r0+8]);
            }
#pragma unroll
            for (int nt = 0; nt < 4; nt++) {
                int cn = wc*32 + nt*8 + gid;
                bf[nt][0] = __float_as_uint(Ws[cur][kk+tig  ][cn]);
                bf[nt][1] = __float_as_uint(Ws[cur][kk+tig+4][cn]);
            }
#pragma unroll
            for (int mt = 0; mt < 4; mt++)
#pragma unroll
                for (int nt = 0; nt < 4; nt++)
                    mma_tf32(acc[mt][nt], af[mt], bf[nt]);
        }
        if (more) {
            int nxt = 1 - cur;
#pragma unroll
            for (int q = 0; q < 8; q++) { As[nxt][akoff+q][arow] = ra[q]; Ws[nxt][akoff+q][arow] = to_tf32(rw[q]); }
            __syncthreads();
        }
    }

    float* Cb = C + (size_t)blockIdx.z * M * Nout;
#pragma unroll
    for (int mt = 0; mt < 4; mt++) {
#pragma unroll
        for (int nt = 0; nt < 4; nt++) {
            int rbase = i0 + wr*64 + mt*16 + gid;
            int cbase = j0 + wc*32 + nt*8 + tig*2;
#pragma unroll
            for (int v = 0; v < 4; v++) {
                int row = rbase + ((v >= 2) ? 8 : 0);
                int col = cbase + (v & 1);
                if (row >= M || col >= Nout) continue;
                Cb[(size_t)row * Nout + col] = acc[mt][nt][v];
            }
        }
    }
}

// deterministic split-K reduction + bias + relu
__global__ void split_reduce_relu(const float* __restrict__ part, float* __restrict__ dst,
                                  const float* __restrict__ bias) {
    int i = blockIdx.x * blockDim.x + threadIdx.x;
    if (i < Bb*Hh) {
        float s = 0.f;
#pragma unroll
        for (int z = 0; z < KSPLIT; z++) s += part[(size_t)z * Bb * Hh + i];
        s += bias[i % Hh];
        dst[i] = fmaxf(s, 0.f);
    }
}

// ---------------- decoder: fused gather + conv + relu (fp16 feat out) ----------------
__global__ void conv_feat(const float* __restrict__ cw, const float* __restrict__ cb,
                          const int* __restrict__ sidx, const int* __restrict__ oidx,
                          const float* __restrict__ ent, const float* __restrict__ other,
                          __half* __restrict__ feat, int mode) {
    int b = blockIdx.x;
    __shared__ float s1[Hh+2], s2[Hh+2];
    __shared__ float w[Cc*6];
    __shared__ float bb[Cc];
    int t = threadIdx.x;
    if (t < Hh) {
        s1[t+1] = ent[sidx[b]*Hh + t];
        s2[t+1] = mode ? ent[oidx[b]*Hh + t] : other[oidx[b]*Hh + t];
    }
    if (t == 0) { s1[0] = 0.f; s2[0] = 0.f; s1[Hh+1] = 0.f; s2[Hh+1] = 0.f; }
    for (int i = t; i < Cc*6; i += blockDim.x) w[i] = cw[i];
    if (t < Cc) bb[t] = cb[t];
    __syncthreads();
    for (int idx = t; idx < CH; idx += blockDim.x) {
        int c = idx / Hh, i = idx % Hh;
        const float* wc = &w[c*6];
        float v = bb[c]
            + s1[i]*wc[0] + s1[i+1]*wc[1] + s1[i+2]*wc[2]
            + s2[i]*wc[3] + s2[i+1]*wc[4] + s2[i+2]*wc[5];
        feat[(size_t)b*CH + idx] = __float2half_rn(fmaxf(v, 0.f));
    }
}

// ---------------- host ----------------

static void* symaddr(const void* s) { void* p = nullptr; cudaGetSymbolAddress(&p, s); return p; }

extern "C" void kernel_launch(void* const* d_in, const int* in_sizes, int n_in,
                              void* d_out, int out_size) {
    const float* ent_embeds = (const float*)d_in[0];
    const float* rel_embeds = (const float*)d_in[1];
    const float* Wr1  = (const float*)d_in[2];
    const float* Wsl1 = (const float*)d_in[3];
    const float* Wel1 = (const float*)d_in[4];
    const float* Wr2  = (const float*)d_in[5];
    const float* Wsl2 = (const float*)d_in[6];
    const float* Wel2 = (const float*)d_in[7];
    const float* lin_W = (const float*)d_in[8];
    const float* lin_b = (const float*)d_in[9];
    const float* gru_Wih = (const float*)d_in[10];
    const float* gru_Whh = (const float*)d_in[11];
    const float* gru_bih = (const float*)d_in[12];
    const float* gru_bhh = (const float*)d_in[13];
    const float* conve_w = (const float*)d_in[14];
    const float* conve_b = (const float*)d_in[15];
    const float* fce_w = (const float*)d_in[16];
    const float* fce_b = (const float*)d_in[17];
    const float* convr_w = (const float*)d_in[18];
    const float* convr_b = (const float*)d_in[19];
    const float* fcr_w = (const float*)d_in[20];
    const float* fcr_b = (const float*)d_in[21];
    const int* src  = (const int*)d_in[22];
    const int* dst  = (const int*)d_in[23];
    const int* erel = (const int*)d_in[24];
    const int* subj = (const int*)d_in[25];
    const int* relI = (const int*)d_in[26];
    const int* objI = (const int*)d_in[27];
    float* out = (float*)d_out;

    float* p_entA  = (float*)symaddr(g_ent);
    float* p_entB  = (float*)symaddr(g_entB);
    __half* p_entH = (__half*)symaddr(g_entH);
    float* p_h1    = (float*)symaddr(g_h1);
    __half* p_h1H  = (__half*)symaddr(g_h1H);
    float* p_h2    = (float*)symaddr(g_h2);
    float* p_pre   = (float*)symaddr(g_pre);
    float* p_preR  = (float*)symaddr(g_preR);
    float* p_winv  = (float*)symaddr(g_winv);
    float* p_relh  = (float*)symaddr(g_relh);
    float* p_x     = (float*)symaddr(g_x);
    float* p_gi    = (float*)symaddr(g_gi);
    float* p_gh    = (float*)symaddr(g_gh);
    int* p_relBase = (int*)symaddr(g_relBase);
    int* p_edgeByRel = (int*)symaddr(g_edgeByRel);
    int* p_nodeBase = (int*)symaddr(g_nodeBase);
    int* p_edgeByDst = (int*)symaddr(g_edgeByDst);
    float* p_rnorm = (float*)symaddr(g_rnorm);
    int* p_zeroList = (int*)symaddr(g_zeroList);
    int* p_zeroCnt = (int*)symaddr(g_zeroCnt);
    __half* p_featA = (__half*)symaddr(g_featA);
    __half* p_featB = (__half*)symaddr(g_featB);
    float* p_decA  = (float*)symaddr(g_decA);
    float* p_decB  = (float*)symaddr(g_decB);
    float* p_partA = (float*)symaddr(g_partA);
    float* p_partB = (float*)symaddr(g_partB);

    const float* Wr_[2]  = {Wr1, Wr2};
    const float* Wsl_[2] = {Wsl1, Wsl2};
    const float* Wel_[2] = {Wel1, Wel2};

    #define TGX(Nc) (((Nc)+127)/128)
    #define TGY(Mr) (((Mr)+127)/128)

    // One-time stream/event creation + smem attribute (host-side resource
    // init; identical GPU work enqueued every call). Per-call creation
    // allocated device memory during graph capture → harness guard.
    static cudaStream_t sP = nullptr, sR = nullptr, s2 = nullptr;
    static cudaEvent_t evRoot, evPrep, evF, evJ, evE[Tt], evG[Tt];
    if (sP == nullptr) {
        cudaStreamCreate(&sP);
        cudaStreamCreate(&sR);
        cudaStreamCreate(&s2);
        cudaEventCreateWithFlags(&evRoot, cudaEventDisableTiming);
        cudaEventCreateWithFlags(&evPrep, cudaEventDisableTiming);
        cudaEventCreateWithFlags(&evF, cudaEventDisableTiming);
        cudaEventCreateWithFlags(&evJ, cudaEventDisableTiming);
        for (int t = 0; t < Tt; t++) {
            cudaEventCreateWithFlags(&evE[t], cudaEventDisableTiming);
            cudaEventCreateWithFlags(&evG[t], cudaEventDisableTiming);
        }
        cudaFuncSetAttribute(rgcn_fused, cudaFuncAttributeMaxDynamicSharedMemorySize, RGCN_SMEM_BYTES);
    }

    // ---- fork: batched 3-step edge preprocessing on sP ----
    cudaEventRecord(evRoot, 0);
    cudaStreamWaitEvent(sP, evRoot, 0);
    zero_prep3<<<dim3((Nn+255)/256, Tt), 256, 0, sP>>>();
    hist3<<<dim3(160, Tt), 256, 0, sP>>>(erel, dst);
    scan_a3<<<dim3(NBLK, Tt), 256, 0, sP>>>();
    scan_mid3<<<dim3(2, Tt), 512, 0, sP>>>();
    scan_c3<<<dim3(NBLK, Tt), 256, 0, sP>>>();
    scatter3<<<dim3((Ee+255)/256, Tt), 256, 0, sP>>>(erel, dst);
    cudaEventRecord(evPrep, sP);

    // ---- init (stream 0, concurrent with prep) ----
    normalize_rows<<<Nn, 256>>>(ent_embeds, p_entA, p_entH, Nn);
    normalize_rows<<<Rr, 256>>>(rel_embeds, p_relh, nullptr, Rr);
    cudaStreamWaitEvent(0, evPrep, 0);

    float* entIn = p_entA;
    float* entOut = p_entB;

    for (int t = 0; t < Tt; t++) {
        const int* srcT  = src  + t*Ee;
        const int* erelT = erel + t*Ee;
        const int* nbT   = p_nodeBase + t*(Nn+1);
        const int* ebdT  = p_edgeByDst + t*Ee;
        const int* rbT   = p_relBase + t*(Rr+1);
        const int* ebrT  = p_edgeByRel + t*Ee;
        const float* rnT = p_rnorm + t*Nn;
        const int* zlT   = p_zeroList + t*Nn;
        const int* zcT   = p_zeroCnt + t;

        // fork: relation-GRU path + preR gather on sR; big h-gather on stream 0
        cudaEventRecord(evE[t], 0);
        cudaStreamWaitEvent(sR, evE[t], 0);

        gather_h<<<Nn/2, 256>>>(srcT, (const __half2*)p_entH, nbT, ebdT);

        rel_mean<<<Rr, 256, 0, sR>>>(srcT, (const __half2*)p_entH, rel_embeds, rbT, ebrT);
        tgemm<4><<<dim3(TGX(3*Hh), TGY(Rr)), 256, 0, sR>>>(p_x, gru_Wih, p_gi, Rr, 3*Hh, 2*Hh, gru_bih, nullptr, nullptr, nullptr);
        tgemm<4><<<dim3(TGX(3*Hh), TGY(Rr)), 256, 0, sR>>>(p_relh, gru_Whh, p_gh, Rr, 3*Hh, Hh, gru_bhh, nullptr, nullptr, nullptr);
        gru_gate<<<Rr, 256, 0, sR>>>();
        gather_radd<<<Nn/2, 256, 0, sR>>>(erelT, nbT, ebdT);   // preR, reused by BOTH layers
        cudaEventRecord(evG[t], sR);
        cudaStreamWaitEvent(0, evG[t], 0);

        rgcn_fused<<<dim3((Hh+63)/64, (Nn+127)/128), 256, RGCN_SMEM_BYTES>>>(entIn, p_pre, p_preR, Wr_[0], Wsl_[0], p_h1, p_h1H, rnT);
        fixup_zero<<<32, 256>>>(Wel_[0], entIn, p_h1, p_h1H, zlT, zcT);

        gather_h<<<Nn/2, 256>>>(srcT, (const __half2*)p_h1H, nbT, ebdT);
        rgcn_fused<<<dim3((Hh+63)/64, (Nn+127)/128), 256, RGCN_SMEM_BYTES>>>(p_h1, p_pre, p_preR, Wr_[1], Wsl_[1], p_h2, nullptr, rnT);
        fixup_zero<<<32, 256>>>(Wel_[1], p_h1, p_h2, nullptr, zlT, zcT);

        // entity update: parallel row-norm then fused sigmoid-gate GEMM
        rownorm_inv<<<(Nn + 7)/8, 256>>>();
        tgemm<5><<<dim3(TGX(Hh), TGY(Nn)), 256>>>(entIn, lin_W, entOut, Nn, Hh, Hh, lin_b, p_h2, p_winv, p_entH);

        float* tmp = entIn; entIn = entOut; entOut = tmp;
    }
    float* entF = entIn;

    const int klen = CH / KSPLIT;   // 1000

    // ---- decoder: fork into two streams ----
    cudaEventRecord(evF, 0);
    cudaStreamWaitEvent(s2, evF, 0);

    // obj branch (stream 0)
    conv_feat<<<Bb, 256>>>(conve_w, conve_b, subj, relI, entF, p_relh, p_featA, 0);
    tgemmH_split<<<dim3(TGX(Hh), TGY(Bb), KSPLIT), 256>>>(p_featA, fce_w, p_partA, Bb, Hh, CH, klen);
    split_reduce_relu<<<(Bb*Hh + 255)/256, 256>>>(p_partA, p_decA, fce_b);
    tgemm<0><<<dim3(TGX(Nn), TGY(Bb)), 256>>>(p_decA, entF, out, Bb, Nn, Hh, nullptr, nullptr, nullptr, nullptr);

    // rel branch (stream s2)
    conv_feat<<<Bb, 256, 0, s2>>>(convr_w, convr_b, subj, objI, entF, p_relh, p_featB, 1);
    tgemmH_split<<<dim3(TGX(Hh), TGY(Bb), KSPLIT), 256, 0, s2>>>(p_featB, fcr_w, p_partB, Bb, Hh, CH, klen);
    split_reduce_relu<<<(Bb*Hh + 255)/256, 256, 0, s2>>>(p_partB, p_decB, fcr_b);
    tgemm<0><<<dim3(TGX(Rr), TGY(Bb)), 256, 0, s2>>>(p_decB, p_relh, out + (size_t)Bb*Nn, Bb, Rr, Hh, nullptr, nullptr, nullptr, nullptr);

    cudaEventRecord(evJ, s2);
    cudaStreamWaitEvent(0, evJ, 0);
}

// round 17
// speedup vs baseline: 1.0940x; 1.0463x over previous
#include <cuda_runtime.h>
#include <cuda_fp16.h>
#include <math.h>
#include <stdint.h>

#define Nn 20000
#define Rr 400
#define Hh 200
#define Ee 200000
#define Tt 3
#define Bb 1024
#define Cc 50
#define CH (Cc*Hh)
#define KSPLIT 10
#define NBLK ((Nn + 255) / 256)
#define SLOPEC 0.22916666666666666f
#define EPSN 1e-12f

// ---------------- scratch (device globals; no allocation allowed) ----------------
__device__ float g_ent[Nn*Hh];
__device__ float g_entB[Nn*Hh];
__device__ __half g_entH[Nn*Hh];
__device__ float g_h1[Nn*Hh];
__device__ __half g_h1H[Nn*Hh];
__device__ float g_h2[Nn*Hh];
__device__ float g_pre[Nn*Hh];
__device__ float g_winv[Nn];
__device__ float g_relh[Rr*Hh];
__device__ float g_x[Rr*2*Hh];
__device__ float g_gi[Rr*3*Hh];
__device__ float g_gh[Rr*3*Hh];
__device__ float g_nrel[Rr*Hh];
// per-timestep (x3) preprocessing buffers
__device__ int   g_relCnt[Tt*Rr];
__device__ int   g_relBase[Tt*(Rr+1)];
__device__ int   g_relCur[Tt*Rr];
__device__ int   g_edgeByRel[Tt*Ee];
__device__ int   g_degCnt[Tt*Nn];
__device__ int   g_nodeBase[Tt*(Nn+1)];
__device__ int   g_nodeCur[Tt*Nn];
__device__ int   g_edgeByDst[Tt*Ee];
__device__ int   g_blkSum[Tt*NBLK];
__device__ int   g_blkOff[Tt*NBLK];
__device__ float g_rnorm[Tt*Nn];
__device__ int   g_zeroList[Tt*Nn];
__device__ int   g_zeroCnt[Tt];
// decoder
__device__ __half g_featA[Bb*CH];
__device__ __half g_featB[Bb*CH];
__device__ float g_decA[Bb*Hh];
__device__ float g_decB[Bb*Hh];
__device__ float g_partA[KSPLIT*Bb*Hh];
__device__ float g_partB[KSPLIT*Bb*Hh];

// ---------------- tf32 helpers ----------------
__device__ __forceinline__ float to_tf32(float x) {
    uint32_t u;
    asm("cvt.rna.tf32.f32 %0, %1;" : "=r"(u) : "r"(__float_as_uint(x)));
    return __uint_as_float(u);
}

__device__ __forceinline__ void mma_tf32(float* d, const uint32_t* a, const uint32_t* b) {
    asm volatile(
        "mma.sync.aligned.m16n8k8.row.col.f32.tf32.tf32.f32 "
        "{%0,%1,%2,%3}, {%4,%5,%6,%7}, {%8,%9}, {%0,%1,%2,%3};\n"
        : "+f"(d[0]), "+f"(d[1]), "+f"(d[2]), "+f"(d[3])
        : "r"(a[0]), "r"(a[1]), "r"(a[2]), "r"(a[3]),
          "r"(b[0]), "r"(b[1]));
}

// predicated 8-float row load into regs
__device__ __forceinline__ void ld_row8(const float* __restrict__ base, int gka, int kmax,
                                        bool ok, float* r) {
    if (ok && gka + 8 <= kmax) {
        float4 v0 = *reinterpret_cast<const float4*>(base + gka);
        float4 v1 = *reinterpret_cast<const float4*>(base + gka + 4);
        r[0]=v0.x; r[1]=v0.y; r[2]=v0.z; r[3]=v0.w;
        r[4]=v1.x; r[5]=v1.y; r[6]=v1.z; r[7]=v1.w;
    } else {
#pragma unroll
        for (int q = 0; q < 8; q++) r[q] = (ok && gka + q < kmax) ? base[gka + q] : 0.f;
    }
}

// predicated 4-float row load into regs
__device__ __forceinline__ void ld_row4(const float* __restrict__ base, int gkw, int kmax,
                                        bool ok, float* r) {
    if (ok && gkw + 4 <= kmax) {
        float4 v = *reinterpret_cast<const float4*>(base + gkw);
        r[0]=v.x; r[1]=v.y; r[2]=v.z; r[3]=v.w;
    } else {
#pragma unroll
        for (int q = 0; q < 4; q++) r[q] = (ok && gkw + q < kmax) ? base[gkw + q] : 0.f;
    }
}

// predicated 8-half row load into regs (as floats)
__device__ __forceinline__ void ld_row8h(const __half* __restrict__ base, int gka, int kmax,
                                         bool ok, float* r) {
    if (ok && gka + 8 <= kmax) {
        uint4 raw = *reinterpret_cast<const uint4*>(base + gka);
        float2 f0 = __half22float2(*reinterpret_cast<__half2*>(&raw.x));
        float2 f1 = __half22float2(*reinterpret_cast<__half2*>(&raw.y));
        float2 f2 = __half22float2(*reinterpret_cast<__half2*>(&raw.z));
        float2 f3 = __half22float2(*reinterpret_cast<__half2*>(&raw.w));
        r[0]=f0.x; r[1]=f0.y; r[2]=f1.x; r[3]=f1.y;
        r[4]=f2.x; r[5]=f2.y; r[6]=f3.x; r[7]=f3.y;
    } else {
#pragma unroll
        for (int q = 0; q < 8; q++) r[q] = (ok && gka + q < kmax) ? __half2float(base[gka + q]) : 0.f;
    }
}

// ---------------- batched (all timesteps) preprocessing ----------------

__global__ void zero_prep3() {
    int tt = blockIdx.y;
    int i = blockIdx.x * blockDim.x + threadIdx.x;
    if (i < Nn) g_degCnt[tt*Nn + i] = 0;
    if (i < Rr) g_relCnt[tt*Rr + i] = 0;
    if (i == 0) g_zeroCnt[tt] = 0;
}

__global__ void hist3(const int* __restrict__ erel_all, const int* __restrict__ dst_all) {
    int tt = blockIdx.y;
    const int* er = erel_all + tt*Ee;
    const int* ds = dst_all + tt*Ee;
    __shared__ int sh[Rr];
    for (int i = threadIdx.x; i < Rr; i += blockDim.x) sh[i] = 0;
    __syncthreads();
    for (int e = blockIdx.x * blockDim.x + threadIdx.x; e < Ee; e += gridDim.x * blockDim.x) {
        atomicAdd(&sh[er[e]], 1);
        atomicAdd(&g_degCnt[tt*Nn + ds[e]], 1);
    }
    __syncthreads();
    for (int i = threadIdx.x; i < Rr; i += blockDim.x)
        if (sh[i]) atomicAdd(&g_relCnt[tt*Rr + i], sh[i]);
}

__global__ void scan_a3() {
    int tt = blockIdx.y;
    int b = blockIdx.x, t = threadIdx.x, i = b*256 + t;
    int v = (i < Nn) ? g_degCnt[tt*Nn + i] : 0;
    int lane = t & 31, w = t >> 5;
    int s = v;
#pragma unroll
    for (int o = 1; o < 32; o <<= 1) {
        int y = __shfl_up_sync(0xffffffffu, s, o);
        if (lane >= o) s += y;
    }
    __shared__ int wsum[8];
    if (lane == 31) wsum[w] = s;
    __syncthreads();
    if (w == 0 && lane < 8) {
        int x = wsum[lane];
#pragma unroll
        for (int o = 1; o < 8; o <<= 1) {
            int y = __shfl_up_sync(0xffu, x, o);
            if (lane >= o) x += y;
        }
        wsum[lane] = x;
    }
    __syncthreads();
    int incl = s + (w > 0 ? wsum[w-1] : 0);
    if (i < Nn) g_nodeBase[tt*(Nn+1) + i] = incl - v;
    if (t == 255) g_blkSum[tt*NBLK + b] = incl;
}

__global__ void scan_mid3() {
    int tt = blockIdx.y;
    __shared__ int sm[512];
    int t = threadIdx.x;
    if (blockIdx.x == 0) {
        int v = (t < NBLK) ? g_blkSum[tt*NBLK + t] : 0;
        sm[t] = v;
        __syncthreads();
        for (int o = 1; o < 512; o <<= 1) {
            int y = (t >= o) ? sm[t-o] : 0;
            __syncthreads();
            sm[t] += y;
            __syncthreads();
        }
        if (t < NBLK) g_blkOff[tt*NBLK + t] = sm[t] - v;
    } else {
        int v = (t < Rr) ? g_relCnt[tt*Rr + t] : 0;
        sm[t] = v;
        __syncthreads();
        for (int o = 1; o < 512; o <<= 1) {
            int y = (t >= o) ? sm[t-o] : 0;
            __syncthreads();
            sm[t] += y;
            __syncthreads();
        }
        if (t < Rr) { int e = sm[t] - v; g_relBase[tt*(Rr+1) + t] = e; g_relCur[tt*Rr + t] = e; }
        if (t == 0) g_relBase[tt*(Rr+1) + Rr] = Ee;
    }
}

__global__ void scan_c3() {
    int tt = blockIdx.y;
    int b = blockIdx.x, i = b*256 + threadIdx.x;
    if (i < Nn) {
        int x = g_nodeBase[tt*(Nn+1) + i] + g_blkOff[tt*NBLK + b];
        g_nodeBase[tt*(Nn+1) + i] = x;
        g_nodeCur[tt*Nn + i] = x;
        int d = g_degCnt[tt*Nn + i];
        g_rnorm[tt*Nn + i] = d > 0 ? 1.0f / (float)d : 0.0f;
        if (d == 0) {
            int k = atomicAdd(&g_zeroCnt[tt], 1);
            g_zeroList[tt*Nn + k] = i;
        }
    }
    if (i == 0) g_nodeBase[tt*(Nn+1) + Nn] = Ee;
}

__global__ void scatter3(const int* __restrict__ erel_all, const int* __restrict__ dst_all) {
    int tt = blockIdx.y;
    const int* er = erel_all + tt*Ee;
    const int* ds = dst_all + tt*Ee;
    int e = blockIdx.x * blockDim.x + threadIdx.x;
    if (e < Ee) {
        int p1 = atomicAdd(&g_relCur[tt*Rr + er[e]], 1);
        g_edgeByRel[tt*Ee + p1] = e;
        int p2 = atomicAdd(&g_nodeCur[tt*Nn + ds[e]], 1);
        g_edgeByDst[tt*Ee + p2] = e;
    }
}

// ---------------- utility kernels ----------------

__global__ void normalize_rows(const float* __restrict__ in, float* __restrict__ out,
                               __half* __restrict__ outH, int rows) {
    int r = blockIdx.x;
    if (r >= rows) return;
    __shared__ float red[256];
    int t = threadIdx.x;
    float v = (t < Hh) ? in[r*Hh + t] : 0.f;
    red[t] = v*v;
    __syncthreads();
    for (int s = 128; s > 0; s >>= 1) { if (t < s) red[t] += red[t+s]; __syncthreads(); }
    float inv = 1.0f / fmaxf(sqrtf(red[0]), EPSN);
    if (t < Hh) {
        float x = v * inv;
        out[r*Hh + t] = x;
        if (outH) outH[r*Hh + t] = __float2half_rn(x);
    }
}

// per-relation mean of entH[src] + build GRU input x
__global__ void rel_mean(const int* __restrict__ srcT, const __half2* __restrict__ entH2,
                         const float* __restrict__ rel_embeds,
                         const int* __restrict__ relBase, const int* __restrict__ edgeByRel) {
    __shared__ int ss[256];
    int r = blockIdx.x, t = threadIdx.x;
    int b0 = relBase[r], b1 = relBase[r+1];
    float2 acc = make_float2(0.f, 0.f);
    for (int cb = b0; cb < b1; cb += 256) {
        int m = min(256, b1 - cb);
        if (t < m) ss[t] = srcT[edgeByRel[cb + t]];
        __syncthreads();
        if (t < Hh/2) {
#pragma unroll 4
            for (int i = 0; i < m; i++) {
                float2 f = __half22float2(entH2[ss[i]*(Hh/2) + t]);
                acc.x += f.x; acc.y += f.y;
            }
        }
        __syncthreads();
    }
    if (t < Hh) g_x[r*2*Hh + t] = rel_embeds[r*Hh + t];
    if (t < Hh/2) {
        int cnt = b1 - b0;
        float invc = cnt > 0 ? 1.0f / (float)cnt : 0.f;
        g_x[r*2*Hh + Hh + 2*t]     = acc.x * invc;
        g_x[r*2*Hh + Hh + 2*t + 1] = acc.y * invc;
    }
}

// GRU gates + l2norm; writes n_rel and relh
__global__ void gru_gate() {
    int r = blockIdx.x, t = threadIdx.x;
    __shared__ float red[256];
    float hp = 0.f;
    if (t < Hh) {
        const float* gi = &g_gi[r*3*Hh];
        const float* gh = &g_gh[r*3*Hh];
        float h  = g_relh[r*Hh + t];
        float rr = 1.f / (1.f + expf(-(gi[t]        + gh[t])));
        float z  = 1.f / (1.f + expf(-(gi[Hh+t]     + gh[Hh+t])));
        float n  = tanhf(gi[2*Hh+t] + rr * gh[2*Hh+t]);
        hp = (1.f - z) * n + z * h;
    }
    red[t] = hp*hp;
    __syncthreads();
    for (int s = 128; s > 0; s >>= 1) { if (t < s) red[t] += red[t+s]; __syncthreads(); }
    float inv = 1.0f / fmaxf(sqrtf(red[0]), EPSN);
    if (t < Hh) {
        float v = hp * inv;
        g_nrel[r*Hh + t] = v;
        g_relh[r*Hh + t] = v;
    }
}

// gather_h: pre[n] = sum over in-edges of hinH[src]
__global__ void gather_h(const int* __restrict__ srcT, const __half2* __restrict__ hinH2,
                         const int* __restrict__ nodeBase, const int* __restrict__ edgeByDst) {
    __shared__ int ss[2][32];
    __shared__ int maxlen;
    int half_id = threadIdx.x >> 7;
    int t = threadIdx.x & 127;
    int n = blockIdx.x * 2 + half_id;
    int b0 = nodeBase[n], b1 = nodeBase[n+1];
    int len = b1 - b0;
    if (threadIdx.x == 0) maxlen = 0;
    __syncthreads();
    if (t == 0) atomicMax(&maxlen, len);
    __syncthreads();
    float2 acc = make_float2(0.f, 0.f);
    int ml = maxlen;
    for (int cb = 0; cb < ml; cb += 32) {
        int m = min(32, len - cb);
        if (t < m) ss[half_id][t] = srcT[edgeByDst[b0 + cb + t]];
        __syncthreads();
        if (t < Hh/2) {
#pragma unroll 4
            for (int i = 0; i < m; i++) {
                float2 h = __half22float2(hinH2[ss[half_id][i]*(Hh/2) + t]);
                acc.x += h.x; acc.y += h.y;
            }
        }
        __syncthreads();
    }
    if (t < Hh/2) ((float2*)g_pre)[n*(Hh/2) + t] = acc;
}

// gather_radd: pre[n] += sum over in-edges of nrel[erel]  (RMW into g_pre)
__global__ void gather_radd(const int* __restrict__ erelT,
                            const int* __restrict__ nodeBase, const int* __restrict__ edgeByDst) {
    __shared__ int rs[2][32];
    __shared__ int maxlen;
    int half_id = threadIdx.x >> 7;
    int t = threadIdx.x & 127;
    int n = blockIdx.x * 2 + half_id;
    int b0 = nodeBase[n], b1 = nodeBase[n+1];
    int len = b1 - b0;
    if (threadIdx.x == 0) maxlen = 0;
    __syncthreads();
    if (t == 0) atomicMax(&maxlen, len);
    __syncthreads();
    const float2* nrel2 = (const float2*)g_nrel;
    float2 acc = make_float2(0.f, 0.f);
    int ml = maxlen;
    for (int cb = 0; cb < ml; cb += 32) {
        int m = min(32, len - cb);
        if (t < m) rs[half_id][t] = erelT[edgeByDst[b0 + cb + t]];
        __syncthreads();
        if (t < Hh/2) {
#pragma unroll 4
            for (int i = 0; i < m; i++) {
                float2 r = nrel2[rs[half_id][i]*(Hh/2) + t];
                acc.x += r.x; acc.y += r.y;
            }
        }
        __syncthreads();
    }
    if (t < Hh/2) {
        float2 p = ((float2*)g_pre)[n*(Hh/2) + t];
        p.x += acc.x; p.y += acc.y;
        ((float2*)g_pre)[n*(Hh/2) + t] = p;
    }
}

// combined gather (h + nrel) for layer 2
__global__ void gather_pre(const int* __restrict__ srcT, const int* __restrict__ erelT,
                           const __half2* __restrict__ hinH2,
                           const int* __restrict__ nodeBase, const int* __restrict__ edgeByDst) {
    __shared__ int ss[2][32];
    __shared__ int rs[2][32];
    __shared__ int maxlen;
    int half_id = threadIdx.x >> 7;
    int t = threadIdx.x & 127;
    int n = blockIdx.x * 2 + half_id;
    int b0 = nodeBase[n], b1 = nodeBase[n+1];
    int len = b1 - b0;
    if (threadIdx.x == 0) maxlen = 0;
    __syncthreads();
    if (t == 0) atomicMax(&maxlen, len);
    __syncthreads();
    const float2* nrel2 = (const float2*)g_nrel;
    float2 acc = make_float2(0.f, 0.f);
    int ml = maxlen;
    for (int cb = 0; cb < ml; cb += 32) {
        int m = min(32, len - cb);
        if (t < m) {
            int e = edgeByDst[b0 + cb + t];
            ss[half_id][t] = srcT[e];
            rs[half_id][t] = erelT[e];
        }
        __syncthreads();
        if (t < Hh/2) {
#pragma unroll 4
            for (int i = 0; i < m; i++) {
                float2 h = __half22float2(hinH2[ss[half_id][i]*(Hh/2) + t]);
                float2 r = nrel2[rs[half_id][i]*(Hh/2) + t];
                acc.x += h.x + r.x;
                acc.y += h.y + r.y;
            }
        }
        __syncthreads();
    }
    if (t < Hh/2) ((float2*)g_pre)[n*(Hh/2) + t] = acc;
}

// deg==0 rows: out = rrelu(hin @ Wel^T)
__global__ void fixup_zero(const float* __restrict__ Wel, const float* __restrict__ hin,
                           float* __restrict__ hout, __half* __restrict__ houtH,
                           const int* __restrict__ zeroList, const int* __restrict__ zeroCnt) {
    __shared__ float hrow[Hh];
    int zc = *zeroCnt;
    for (int li = blockIdx.x; li < zc; li += gridDim.x) {
        int n = zeroList[li];
        int t = threadIdx.x;
        if (t < Hh) hrow[t] = hin[n*Hh + t];
        __syncthreads();
        if (t < Hh) {
            float s = 0.f;
            for (int k = 0; k < Hh; k++) s += hrow[k] * Wel[t*Hh + k];
            s = s >= 0.f ? s : SLOPEC * s;
            hout[n*Hh + t] = s;
            if (houtH) houtH[n*Hh + t] = __float2half_rn(s);
        }
        __syncthreads();
    }
}

__global__ void rownorm_inv() {
    int row = blockIdx.x * 8 + (threadIdx.x >> 5);
    int lane = threadIdx.x & 31;
    if (row >= Nn) return;
    float s = 0.f;
    for (int c = lane; c < Hh; c += 32) { float v = g_h2[row*Hh + c]; s += v*v; }
    for (int o = 16; o > 0; o >>= 1) s += __shfl_xor_sync(0xffffffff, s, o);
    if (lane == 0) g_winv[row] = 1.0f / fmaxf(sqrtf(s), EPSN);
}

// ---------------- fused RGCN layer (double-buffered, dynamic smem) ----------------
#define FPA 136
#define FPW 72
#define RGCN_SMEM_FLOATS (4*16*FPA + 4*16*FPW)
#define RGCN_SMEM_BYTES (RGCN_SMEM_FLOATS * 4)
__global__ void __launch_bounds__(256)
rgcn_fused(const float* __restrict__ hin, const float* __restrict__ pre,
           const float* __restrict__ Wr, const float* __restrict__ Wsl,
           float* __restrict__ hout, __half* __restrict__ houtH,
           const float* __restrict__ rnorm) {
    extern __shared__ float dsm[];
    float (*Ah)[16][FPA] = (float(*)[16][FPA])(dsm);
    float (*Ap)[16][FPA] = (float(*)[16][FPA])(dsm + 2*16*FPA);
    float (*Sr)[16][FPW] = (float(*)[16][FPW])(dsm + 4*16*FPA);
    float (*Ss)[16][FPW] = (float(*)[16][FPW])(dsm + 4*16*FPA + 2*16*FPW);

    int tid = threadIdx.x;
    int j0 = blockIdx.x * 64;
    int i0 = blockIdx.y * 128;
    int wid = tid >> 5, lane = tid & 31;
    int wr = wid & 1, wc = wid >> 1;
    int gid = lane >> 2, tig = lane & 3;

    float accR[4][2][4], accS[4][2][4];
#pragma unroll
    for (int a = 0; a < 4; a++)
#pragma unroll
        for (int b = 0; b < 2; b++)
#pragma unroll
            for (int v = 0; v < 4; v++) { accR[a][b][v] = 0.f; accS[a][b][v] = 0.f; }

    int arow = tid >> 1;
    int akoff = (tid & 1) * 8;
    int gr = i0 + arow;
    bool rok = gr < Nn;
    const float* hrow = hin + (size_t)gr * Hh;
    const float* prow = pre + (size_t)gr * Hh;

    int wrow = tid >> 2;
    int wkoff = (tid & 3) * 4;
    int gw = j0 + wrow;
    bool wok = gw < Hh;
    const float* wrp = Wr  + (size_t)gw * Hh;
    const float* wsp = Wsl + (size_t)gw * Hh;

    const int NK = (Hh + 15) / 16;   // 13
    float rh[8], rp[8], rr4[4], rs4[4];

    ld_row8(hrow, akoff, Hh, rok, rh);
    ld_row8(prow, akoff, Hh, rok, rp);
    ld_row4(wrp, wkoff, Hh, wok, rr4);
    ld_row4(wsp, wkoff, Hh, wok, rs4);
#pragma unroll
    for (int q = 0; q < 8; q++) { Ah[0][akoff+q][arow] = to_tf32(rh[q]); Ap[0][akoff+q][arow] = to_tf32(rp[q]); }
#pragma unroll
    for (int q = 0; q < 4; q++) { Sr[0][wkoff+q][wrow] = to_tf32(rr4[q]); Ss[0][wkoff+q][wrow] = to_tf32(rs4[q]); }
    __syncthreads();

    for (int it = 0; it < NK; it++) {
        int cur = it & 1;
        bool more = (it + 1 < NK);
        if (more) {
            int kt = (it + 1) * 16;
            ld_row8(hrow, kt + akoff, Hh, rok, rh);
            ld_row8(prow, kt + akoff, Hh, rok, rp);
            ld_row4(wrp, kt + wkoff, Hh, wok, rr4);
            ld_row4(wsp, kt + wkoff, Hh, wok, rs4);
        }
#pragma unroll
        for (int kk = 0; kk < 16; kk += 8) {
            uint32_t ah[4][4], ap[4][4];
#pragma unroll
            for (int mt = 0; mt < 4; mt++) {
                int r0 = wr*64 + mt*16 + gid;
                ah[mt][0] = __float_as_uint(Ah[cur][kk+tig  ][r0]);
                ah[mt][1] = __float_as_uint(Ah[cur][kk+tig  ][r0+8]);
                ah[mt][2] = __float_as_uint(Ah[cur][kk+tig+4][r0]);
                ah[mt][3] = __float_as_uint(Ah[cur][kk+tig+4][r0+8]);
                ap[mt][0] = __float_as_uint(Ap[cur][kk+tig  ][r0]);
                ap[mt][1] = __float_as_uint(Ap[cur][kk+tig  ][r0+8]);
                ap[mt][2] = __float_as_uint(Ap[cur][kk+tig+4][r0]);
                ap[mt][3] = __float_as_uint(Ap[cur][kk+tig+4][r0+8]);
            }
            uint32_t br[2][2], bs[2][2];
#pragma unroll
            for (int nt = 0; nt < 2; nt++) {
                int cn = wc*16 + nt*8 + gid;
                br[nt][0] = __float_as_uint(Sr[cur][kk+tig  ][cn]);
                br[nt][1] = __float_as_uint(Sr[cur][kk+tig+4][cn]);
                bs[nt][0] = __float_as_uint(Ss[cur][kk+tig  ][cn]);
                bs[nt][1] = __float_as_uint(Ss[cur][kk+tig+4][cn]);
            }
#pragma unroll
            for (int mt = 0; mt < 4; mt++)
#pragma unroll
                for (int nt = 0; nt < 2; nt++) {
                    mma_tf32(accR[mt][nt], ap[mt], br[nt]);
                    mma_tf32(accS[mt][nt], ah[mt], bs[nt]);
                }
        }
        if (more) {
            int nxt = 1 - cur;
#pragma unroll
            for (int q = 0; q < 8; q++) { Ah[nxt][akoff+q][arow] = to_tf32(rh[q]); Ap[nxt][akoff+q][arow] = to_tf32(rp[q]); }
#pragma unroll
            for (int q = 0; q < 4; q++) { Sr[nxt][wkoff+q][wrow] = to_tf32(rr4[q]); Ss[nxt][wkoff+q][wrow] = to_tf32(rs4[q]); }
            __syncthreads();
        }
    }

#pragma unroll
    for (int mt = 0; mt < 4; mt++) {
#pragma unroll
        for (int nt = 0; nt < 2; nt++) {
            int rbase = i0 + wr*64 + mt*16 + gid;
            int cbase = j0 + wc*16 + nt*8 + tig*2;
#pragma unroll
            for (int v = 0; v < 4; v++) {
                int row = rbase + ((v >= 2) ? 8 : 0);
                int col = cbase + (v & 1);
                if (row >= Nn || col >= Hh) continue;
                float x = accR[mt][nt][v] * rnorm[row] + accS[mt][nt][v];
                x = x >= 0.f ? x : SLOPEC * x;
                hout[(size_t)row * Hh + col] = x;
                if (houtH) houtH[(size_t)row * Hh + col] = __float2half_rn(x);
            }
        }
    }
}

// ---------------- tf32 GEMM (fp32 A), double-buffered: C = epi(A @ W^T) ----------------
// EPI: 0 plain | 4 acc+bias | 5 fused gate-update (rowscale = precomputed h2 row-norm inv)
#define TPAD 136
template<int EPI>
__global__ void __launch_bounds__(256)
tgemm(const float* __restrict__ A, const float* __restrict__ W,
      float* __restrict__ C, int M, int Nout, int Kdim,
      const float* __restrict__ bias,
      const float* __restrict__ Sadd,
      const float* __restrict__ rowscale,
      __half* __restrict__ Chalf) {
    __shared__ float As[2][16][TPAD];
    __shared__ float Ws[2][16][TPAD];
    int tid = threadIdx.x;
    int j0 = blockIdx.x * 128;
    int i0 = blockIdx.y * 128;

    int wid = tid >> 5, lane = tid & 31;
    int wr = wid & 1, wc = wid >> 1;
    int gid = lane >> 2, tig = lane & 3;

    float acc[4][4][4];
#pragma unroll
    for (int a = 0; a < 4; a++)
#pragma unroll
        for (int b = 0; b < 4; b++)
#pragma unroll
            for (int v = 0; v < 4; v++) acc[a][b][v] = 0.f;

    int arow = tid >> 1;
    int akoff = (tid & 1) * 8;
    int gr = i0 + arow;
    int gw = j0 + arow;
    bool rok = gr < M;
    bool wok = gw < Nout;
    const float* Arow_p = A + (size_t)gr * Kdim;
    const float* Wrow_p = W + (size_t)gw * Kdim;

    const int NK = (Kdim + 15) / 16;
    float ra[8], rw[8];

    ld_row8(Arow_p, akoff, Kdim, rok, ra);
    ld_row8(Wrow_p, akoff, Kdim, wok, rw);
#pragma unroll
    for (int q = 0; q < 8; q++) { As[0][akoff+q][arow] = to_tf32(ra[q]); Ws[0][akoff+q][arow] = to_tf32(rw[q]); }
    __syncthreads();

    for (int it = 0; it < NK; it++) {
        int cur = it & 1;
        bool more = (it + 1 < NK);
        if (more) {
            int kt = (it + 1) * 16;
            ld_row8(Arow_p, kt + akoff, Kdim, rok, ra);
            ld_row8(Wrow_p, kt + akoff, Kdim, wok, rw);
        }
#pragma unroll
        for (int kk = 0; kk < 16; kk += 8) {
            uint32_t af[4][4];
            uint32_t bf[4][2];
#pragma unroll
            for (int mt = 0; mt < 4; mt++) {
                int r0 = wr*64 + mt*16 + gid;
                af[mt][0] = __float_as_uint(As[cur][kk+tig  ][r0]);
                af[mt][1] = __float_as_uint(As[cur][kk+tig  ][r0+8]);
                af[mt][2] = __float_as_uint(As[cur][kk+tig+4][r0]);
                af[mt][3] = __float_as_uint(As[cur][kk+tig+4][r0+8]);
            }
#pragma unroll
            for (int nt = 0; nt < 4; nt++) {
                int cn = wc*32 + nt*8 + gid;
                bf[nt][0] = __float_as_uint(Ws[cur][kk+tig  ][cn]);
                bf[nt][1] = __float_as_uint(Ws[cur][kk+tig+4][cn]);
            }
#pragma unroll
            for (int mt = 0; mt < 4; mt++)
#pragma unroll
                for (int nt = 0; nt < 4; nt++)
                    mma_tf32(acc[mt][nt], af[mt], bf[nt]);
        }
        if (more) {
            int nxt = 1 - cur;
#pragma unroll
            for (int q = 0; q < 8; q++) { As[nxt][akoff+q][arow] = to_tf32(ra[q]); Ws[nxt][akoff+q][arow] = to_tf32(rw[q]); }
            __syncthreads();
        }
    }

#pragma unroll
    for (int mt = 0; mt < 4; mt++) {
#pragma unroll
        for (int nt = 0; nt < 4; nt++) {
            int rbase = i0 + wr*64 + mt*16 + gid;
            int cbase = j0 + wc*32 + nt*8 + tig*2;
#pragma unroll
            for (int v = 0; v < 4; v++) {
                int row = rbase + ((v >= 2) ? 8 : 0);
                int col = cbase + (v & 1);
                if (row >= M || col >= Nout) continue;
                float x = acc[mt][nt][v];
                if (EPI == 4) {
                    x += bias[col];
                } else if (EPI == 5) {
                    float u = 1.f / (1.f + expf(-(x + bias[col])));
                    float e = A[(size_t)row * Kdim + col];
                    float w = Sadd[(size_t)row * Nout + col] * rowscale[row];
                    x = e + u * (w - e);
                    Chalf[(size_t)row * Nout + col] = __float2half_rn(x);
                }
                C[(size_t)row * Nout + col] = x;
            }
        }
    }
}

// ---------------- split-K GEMM with fp16 A (double-buffered): raw partials ----------------
__global__ void __launch_bounds__(256)
tgemmH_split(const __half* __restrict__ A, const float* __restrict__ W,
             float* __restrict__ C, int M, int Nout, int Kdim, int klen) {
    __shared__ float As[2][16][TPAD];
    __shared__ float Ws[2][16][TPAD];
    int tid = threadIdx.x;
    int j0 = blockIdx.x * 128;
    int i0 = blockIdx.y * 128;
    int k0 = blockIdx.z * klen;
    int k1 = min(Kdim, k0 + klen);

    int wid = tid >> 5, lane = tid & 31;
    int wr = wid & 1, wc = wid >> 1;
    int gid = lane >> 2, tig = lane & 3;

    float acc[4][4][4];
#pragma unroll
    for (int a = 0; a < 4; a++)
#pragma unroll
        for (int b = 0; b < 4; b++)
#pragma unroll
            for (int v = 0; v < 4; v++) acc[a][b][v] = 0.f;

    int arow = tid >> 1;
    int akoff = (tid & 1) * 8;
    int gr = i0 + arow;
    int gw = j0 + arow;
    bool rok = gr < M;
    bool wok = gw < Nout;
    const __half* Arow_p = A + (size_t)gr * Kdim;
    const float* Wrow_p = W + (size_t)gw * Kdim;

    const int NK = (k1 - k0 + 15) / 16;
    float ra[8], rw[8];

    ld_row8h(Arow_p, k0 + akoff, k1, rok, ra);
    ld_row8(Wrow_p, k0 + akoff, k1, wok, rw);
#pragma unroll
    for (int q = 0; q < 8; q++) { As[0][akoff+q][arow] = ra[q]; Ws[0][akoff+q][arow] = to_tf32(rw[q]); }
    __syncthreads();

    for (int it = 0; it < NK; it++) {
        int cur = it & 1;
        bool more = (it + 1 < NK);
        if (more) {
            int kt = k0 + (it + 1) * 16;
            ld_row8h(Arow_p, kt + akoff, k1, rok, ra);
            ld_row8(Wrow_p, kt + akoff, k1, wok, rw);
        }
#pragma unroll
        for (int kk = 0; kk < 16; kk += 8) {
            uint32_t af[4][4];
            uint32_t bf[4][2];
#pragma unroll
            for (int mt = 0; mt < 4; mt++) {
                int r0 = wr*64 + mt*16 + gid;
                af[mt][0] = __float_as_uint(As[cur][kk+tig  ][r0]);
                af[mt][1] = __float_as_uint(As[cur][kk+tig  ][r0+8]);
                af[mt][2] = __float_as_uint(As[cur][kk+tig+4][r0]);
                af[mt][3] = __float_as_uint(As[cur][kk+tig+4][r0+8]);
            }
#pragma unroll
            for (int nt = 0; nt < 4; nt++) {
                int cn = wc*32 + nt*8 + gid;
                bf[nt][0] = __float_as_uint(Ws[cur][kk+tig  ][cn]);
                bf[nt][1] = __float_as_uint(Ws[cur][kk+tig+4][cn]);
            }
#pragma unroll
            for (int mt = 0; mt < 4; mt++)
#pragma unroll
                for (int nt = 0; nt < 4; nt++)
                    mma_tf32(acc[mt][nt], af[mt], bf[nt]);
        }
        if (more) {
            int nxt = 1 - cur;
#pragma unroll
            for (int q = 0; q < 8; q++) { As[nxt][akoff+q][arow] = ra[q]; Ws[nxt][akoff+q][arow] = to_tf32(rw[q]); }
            __syncthreads();
        }
    }

    float* Cb = C + (size_t)blockIdx.z * M * Nout;
#pragma unroll
    for (int mt = 0; mt < 4; mt++) {
#pragma unroll
        for (int nt = 0; nt < 4; nt++) {
            int rbase = i0 + wr*64 + mt*16 + gid;
            int cbase = j0 + wc*32 + nt*8 + tig*2;
#pragma unroll
            for (int v = 0; v < 4; v++) {
                int row = rbase + ((v >= 2) ? 8 : 0);
                int col = cbase + (v & 1);
                if (row >= M || col >= Nout) continue;
                Cb[(size_t)row * Nout + col] = acc[mt][nt][v];
            }
        }
    }
}

// deterministic split-K reduction + bias + relu
__global__ void split_reduce_relu(const float* __restrict__ part, float* __restrict__ dst,
                                  const float* __restrict__ bias) {
    int i = blockIdx.x * blockDim.x + threadIdx.x;
    if (i < Bb*Hh) {
        float s = 0.f;
#pragma unroll
        for (int z = 0; z < KSPLIT; z++) s += part[(size_t)z * Bb * Hh + i];
        s += bias[i % Hh];
        dst[i] = fmaxf(s, 0.f);
    }
}

// ---------------- decoder: fused gather + conv + relu (fp16 feat out) ----------------
__global__ void conv_feat(const float* __restrict__ cw, const float* __restrict__ cb,
                          const int* __restrict__ sidx, const int* __restrict__ oidx,
                          const float* __restrict__ ent, const float* __restrict__ other,
                          __half* __restrict__ feat, int mode) {
    int b = blockIdx.x;
    __shared__ float s1[Hh+2], s2[Hh+2];
    __shared__ float w[Cc*6];
    __shared__ float bb[Cc];
    int t = threadIdx.x;
    if (t < Hh) {
        s1[t+1] = ent[sidx[b]*Hh + t];
        s2[t+1] = mode ? ent[oidx[b]*Hh + t] : other[oidx[b]*Hh + t];
    }
    if (t == 0) { s1[0] = 0.f; s2[0] = 0.f; s1[Hh+1] = 0.f; s2[Hh+1] = 0.f; }
    for (int i = t; i < Cc*6; i += blockDim.x) w[i] = cw[i];
    if (t < Cc) bb[t] = cb[t];
    __syncthreads();
    for (int idx = t; idx < CH; idx += blockDim.x) {
        int c = idx / Hh, i = idx % Hh;
        const float* wc = &w[c*6];
        float v = bb[c]
            + s1[i]*wc[0] + s1[i+1]*wc[1] + s1[i+2]*wc[2]
            + s2[i]*wc[3] + s2[i+1]*wc[4] + s2[i+2]*wc[5];
        feat[(size_t)b*CH + idx] = __float2half_rn(fmaxf(v, 0.f));
    }
}

// ---------------- host ----------------

static void* symaddr(const void* s) { void* p = nullptr; cudaGetSymbolAddress(&p, s); return p; }

extern "C" void kernel_launch(void* const* d_in, const int* in_sizes, int n_in,
                              void* d_out, int out_size) {
    const float* ent_embeds = (const float*)d_in[0];
    const float* rel_embeds = (const float*)d_in[1];
    const float* Wr1  = (const float*)d_in[2];
    const float* Wsl1 = (const float*)d_in[3];
    const float* Wel1 = (const float*)d_in[4];
    const float* Wr2  = (const float*)d_in[5];
    const float* Wsl2 = (const float*)d_in[6];
    const float* Wel2 = (const float*)d_in[7];
    const float* lin_W = (const float*)d_in[8];
    const float* lin_b = (const float*)d_in[9];
    const float* gru_Wih = (const float*)d_in[10];
    const float* gru_Whh = (const float*)d_in[11];
    const float* gru_bih = (const float*)d_in[12];
    const float* gru_bhh = (const float*)d_in[13];
    const float* conve_w = (const float*)d_in[14];
    const float* conve_b = (const float*)d_in[15];
    const float* fce_w = (const float*)d_in[16];
    const float* fce_b = (const float*)d_in[17];
    const float* convr_w = (const float*)d_in[18];
    const float* convr_b = (const float*)d_in[19];
    const float* fcr_w = (const float*)d_in[20];
    const float* fcr_b = (const float*)d_in[21];
    const int* src  = (const int*)d_in[22];
    const int* dst  = (const int*)d_in[23];
    const int* erel = (const int*)d_in[24];
    const int* subj = (const int*)d_in[25];
    const int* relI = (const int*)d_in[26];
    const int* objI = (const int*)d_in[27];
    float* out = (float*)d_out;

    float* p_entA  = (float*)symaddr(g_ent);
    float* p_entB  = (float*)symaddr(g_entB);
    __half* p_entH = (__half*)symaddr(g_entH);
    float* p_h1    = (float*)symaddr(g_h1);
    __half* p_h1H  = (__half*)symaddr(g_h1H);
    float* p_h2    = (float*)symaddr(g_h2);
    float* p_pre   = (float*)symaddr(g_pre);
    float* p_winv  = (float*)symaddr(g_winv);
    float* p_relh  = (float*)symaddr(g_relh);
    float* p_x     = (float*)symaddr(g_x);
    float* p_gi    = (float*)symaddr(g_gi);
    float* p_gh    = (float*)symaddr(g_gh);
    int* p_relBase = (int*)symaddr(g_relBase);
    int* p_edgeByRel = (int*)symaddr(g_edgeByRel);
    int* p_nodeBase = (int*)symaddr(g_nodeBase);
    int* p_edgeByDst = (int*)symaddr(g_edgeByDst);
    float* p_rnorm = (float*)symaddr(g_rnorm);
    int* p_zeroList = (int*)symaddr(g_zeroList);
    int* p_zeroCnt = (int*)symaddr(g_zeroCnt);
    __half* p_featA = (__half*)symaddr(g_featA);
    __half* p_featB = (__half*)symaddr(g_featB);
    float* p_decA  = (float*)symaddr(g_decA);
    float* p_decB  = (float*)symaddr(g_decB);
    float* p_partA = (float*)symaddr(g_partA);
    float* p_partB = (float*)symaddr(g_partB);

    const float* Wr_[2]  = {Wr1, Wr2};
    const float* Wsl_[2] = {Wsl1, Wsl2};
    const float* Wel_[2] = {Wel1, Wel2};

    #define TGX(Nc) (((Nc)+127)/128)
    #define TGY(Mr) (((Mr)+127)/128)

    // One-time stream/event creation + smem attribute (host-side resource
    // init; identical GPU work enqueued every call). Per-call creation
    // allocated device memory during graph capture → harness guard.
    static cudaStream_t sP = nullptr, sR = nullptr, s2 = nullptr;
    static cudaEvent_t evRoot, evPrep, evF, evJ, evE[Tt], evG[Tt], evP2[Tt];
    if (sP == nullptr) {
        cudaStreamCreate(&sP);
        cudaStreamCreate(&sR);
        cudaStreamCreate(&s2);
        cudaEventCreateWithFlags(&evRoot, cudaEventDisableTiming);
        cudaEventCreateWithFlags(&evPrep, cudaEventDisableTiming);
        cudaEventCreateWithFlags(&evF, cudaEventDisableTiming);
        cudaEventCreateWithFlags(&evJ, cudaEventDisableTiming);
        for (int t = 0; t < Tt; t++) {
            cudaEventCreateWithFlags(&evE[t], cudaEventDisableTiming);
            cudaEventCreateWithFlags(&evG[t], cudaEventDisableTiming);
            cudaEventCreateWithFlags(&evP2[t], cudaEventDisableTiming);
        }
        cudaFuncSetAttribute(rgcn_fused, cudaFuncAttributeMaxDynamicSharedMemorySize, RGCN_SMEM_BYTES);
    }

    // ---- fork: batched 3-step edge preprocessing on sP ----
    cudaEventRecord(evRoot, 0);
    cudaStreamWaitEvent(sP, evRoot, 0);
    zero_prep3<<<dim3((Nn+255)/256, Tt), 256, 0, sP>>>();
    hist3<<<dim3(160, Tt), 256, 0, sP>>>(erel, dst);
    scan_a3<<<dim3(NBLK, Tt), 256, 0, sP>>>();
    scan_mid3<<<dim3(2, Tt), 512, 0, sP>>>();
    scan_c3<<<dim3(NBLK, Tt), 256, 0, sP>>>();
    scatter3<<<dim3((Ee+255)/256, Tt), 256, 0, sP>>>(erel, dst);
    cudaEventRecord(evPrep, sP);

    // ---- init (stream 0, concurrent with prep) ----
    normalize_rows<<<Nn, 256>>>(ent_embeds, p_entA, p_entH, Nn);
    normalize_rows<<<Rr, 256>>>(rel_embeds, p_relh, nullptr, Rr);
    cudaStreamWaitEvent(0, evPrep, 0);

    float* entIn = p_entA;
    float* entOut = p_entB;

    for (int t = 0; t < Tt; t++) {
        const int* srcT  = src  + t*Ee;
        const int* erelT = erel + t*Ee;
        const int* nbT   = p_nodeBase + t*(Nn+1);
        const int* ebdT  = p_edgeByDst + t*Ee;
        const int* rbT   = p_relBase + t*(Rr+1);
        const int* ebrT  = p_edgeByRel + t*Ee;
        const float* rnT = p_rnorm + t*Nn;
        const int* zlT   = p_zeroList + t*Nn;
        const int* zcT   = p_zeroCnt + t;

        // 3-way fork at step start:
        //   sP: gh = relh @ Whh^T (depends only on prev-step relh, ordered via stream 0)
        //   sR: rel_mean -> gi GEMM -> (join gh) -> gru_gate
        //   0 : big h-gather
        cudaEventRecord(evE[t], 0);
        cudaStreamWaitEvent(sR, evE[t], 0);
        cudaStreamWaitEvent(sP, evE[t], 0);

        tgemm<4><<<dim3(TGX(3*Hh), TGY(Rr)), 256, 0, sP>>>(p_relh, gru_Whh, p_gh, Rr, 3*Hh, Hh, gru_bhh, nullptr, nullptr, nullptr);
        cudaEventRecord(evP2[t], sP);

        gather_h<<<Nn/2, 256>>>(srcT, (const __half2*)p_entH, nbT, ebdT);

        rel_mean<<<Rr, 256, 0, sR>>>(srcT, (const __half2*)p_entH, rel_embeds, rbT, ebrT);
        tgemm<4><<<dim3(TGX(3*Hh), TGY(Rr)), 256, 0, sR>>>(p_x, gru_Wih, p_gi, Rr, 3*Hh, 2*Hh, gru_bih, nullptr, nullptr, nullptr);
        cudaStreamWaitEvent(sR, evP2[t], 0);
        gru_gate<<<Rr, 256, 0, sR>>>();
        cudaEventRecord(evG[t], sR);
        cudaStreamWaitEvent(0, evG[t], 0);

        gather_radd<<<Nn/2, 256>>>(erelT, nbT, ebdT);
        rgcn_fused<<<dim3((Hh+63)/64, (Nn+127)/128), 256, RGCN_SMEM_BYTES>>>(entIn, p_pre, Wr_[0], Wsl_[0], p_h1, p_h1H, rnT);
        fixup_zero<<<32, 256>>>(Wel_[0], entIn, p_h1, p_h1H, zlT, zcT);

        gather_pre<<<Nn/2, 256>>>(srcT, erelT, (const __half2*)p_h1H, nbT, ebdT);
        rgcn_fused<<<dim3((Hh+63)/64, (Nn+127)/128), 256, RGCN_SMEM_BYTES>>>(p_h1, p_pre, Wr_[1], Wsl_[1], p_h2, nullptr, rnT);
        fixup_zero<<<32, 256>>>(Wel_[1], p_h1, p_h2, nullptr, zlT, zcT);

        // entity update: parallel row-norm then fused sigmoid-gate GEMM
        rownorm_inv<<<(Nn + 7)/8, 256>>>();
        tgemm<5><<<dim3(TGX(Hh), TGY(Nn)), 256>>>(entIn, lin_W, entOut, Nn, Hh, Hh, lin_b, p_h2, p_winv, p_entH);

        float* tmp = entIn; entIn = entOut; entOut = tmp;
    }
    float* entF = entIn;

    const int klen = CH / KSPLIT;   // 1000

    // ---- decoder: fork into two streams ----
    cudaEventRecord(evF, 0);
    cudaStreamWaitEvent(s2, evF, 0);

    // obj branch (stream 0)
    conv_feat<<<Bb, 256>>>(conve_w, conve_b, subj, relI, entF, p_relh, p_featA, 0);
    tgemmH_split<<<dim3(TGX(Hh), TGY(Bb), KSPLIT), 256>>>(p_featA, fce_w, p_partA, Bb, Hh, CH, klen);
    split_reduce_relu<<<(Bb*Hh + 255)/256, 256>>>(p_partA, p_decA, fce_b);
    tgemm<0><<<dim3(TGX(Nn), TGY(Bb)), 256>>>(p_decA, entF, out, Bb, Nn, Hh, nullptr, nullptr, nullptr, nullptr);

    // rel branch (stream s2)
    conv_feat<<<Bb, 256, 0, s2>>>(convr_w, convr_b, subj, objI, entF, p_relh, p_featB, 1);
    tgemmH_split<<<dim3(TGX(Hh), TGY(Bb), KSPLIT), 256, 0, s2>>>(p_featB, fcr_w, p_partB, Bb, Hh, CH, klen);
    split_reduce_relu<<<(Bb*Hh + 255)/256, 256, 0, s2>>>(p_partB, p_decB, fcr_b);
    tgemm<0><<<dim3(TGX(Rr), TGY(Bb)), 256, 0, s2>>>(p_decB, p_relh, out + (size_t)Bb*Nn, Bb, Rr, Hh, nullptr, nullptr, nullptr, nullptr);

    cudaEventRecord(evJ, s2);
    cudaStreamWaitEvent(0, evJ, 0);
}